// round 12
// baseline (speedup 1.0000x reference)
#include <cuda_runtime.h>
#include <cuda_bf16.h>
#include <math.h>

// Problem constants (fixed bench shapes)
#define BH    32            // B*H = 4*8
#define LSEQ  2048          // sequence length
#define DIM   64            // head dim
#define USEL  40            // u = U_part
#define NCH   32            // key chunks for split-softmax attention
#define CHK   (LSEQ/NCH)    // 64 keys per chunk (single tile per block)
#define KVS   68            // padded smem row stride for attn K/V tiles
#define MCH   512           // m_kernel key-chunk size
#define MQT   512           // m_kernel q-tile (4 tiles x 32 bh = 128 blocks, 1 wave)

// m_kernel smem layout (bytes) — exact R8 layout (best measured: 67.6 us)
#define MS_K     0                                   // 512*64*4   = 131072
#define MS_IDX   (MCH * DIM * 4)                     // +512*40*2  =  40960
#define MS_OFF   (MS_IDX + MQT * USEL * 2)           // +512*4     =   2048
#define M_SMEM   (MS_OFF + MQT * 4)                  // 174080 B (170 KB)

#define A_QS    0
#define A_KS    (USEL * DIM)
#define A_VS    (A_KS + 64 * KVS)
#define A_PT    (A_VS + 64 * KVS)
#define A_SMEM  ((A_PT + 8 * 5 * 64) * 4)            // 55,296 B

// -------- scratch (device globals; no allocation allowed) --------
__device__ unsigned g_Mkey[BH * LSEQ];
__device__ int   g_topk[BH * USEL];
__device__ float g_pm[BH * NCH * USEL];
__device__ float g_pl[BH * NCH * USEL];
__device__ float g_pacc[(size_t)BH * NCH * USEL * DIM];   // 10.5 MB
__device__ unsigned short g_sidx[LSEQ * USEL];      // chunk-sorted, PRE-MASKED local idx
__device__ unsigned g_soff[LSEQ];                   // packed chunk start offsets

__device__ __forceinline__ unsigned f2key(float x) {
    unsigned k = __float_as_uint(x);
    return (k & 0x80000000u) ? ~k : (k | 0x80000000u);
}

// ================= 1. prep: fused mean-of-V + output fill + sample sort ======
// Blocks 0..31: per-bh mean of V, then broadcast-fill that bh's output slab.
// Blocks 32..33: counting-sort sample indices into 4 chunks of 512 (R8 form).
__global__ __launch_bounds__(1024) void prep_kernel(const float* __restrict__ V,
                                                    const int* __restrict__ idxs,
                                                    float4* __restrict__ out,
                                                    int u) {
    if (blockIdx.x < 32) {
        __shared__ float4 sb[64][16];
        int bh = blockIdx.x, t = threadIdx.x;
        int part = t >> 4, c4 = t & 15;
        const float4* Vb = (const float4*)(V + (size_t)bh * LSEQ * DIM);
        float4 s = make_float4(0.f, 0.f, 0.f, 0.f);
        for (int l = part; l < LSEQ; l += 64) {
            float4 v = __ldg(Vb + l * 16 + c4);
            s.x += v.x; s.y += v.y; s.z += v.z; s.w += v.w;
        }
        sb[part][c4] = s;
        __syncthreads();
#pragma unroll
        for (int o = 32; o; o >>= 1) {
            if (part < o) {
                float4 a = sb[part][c4], b = sb[part + o][c4];
                a.x += b.x; a.y += b.y; a.z += b.z; a.w += b.w;
                sb[part][c4] = a;
            }
            __syncthreads();
        }
        float4 mv = sb[0][c4];
        mv.x *= (1.0f / LSEQ); mv.y *= (1.0f / LSEQ);
        mv.z *= (1.0f / LSEQ); mv.w *= (1.0f / LSEQ);
        // fill: thread t writes float4 slots {t, t+1024, ...}; slot&15 == t&15
        float4* ob = out + (size_t)bh * (LSEQ * 16);
        for (int f = t; f < LSEQ * 16; f += 1024)
            ob[f] = mv;
    } else {
        int q = (blockIdx.x - 32) * 1024 + threadIdx.x;
        if (q >= LSEQ) return;
        const int* ip = idxs + (size_t)q * u;
        int cnt[4] = {0, 0, 0, 0};
#pragma unroll
        for (int s = 0; s < USEL; s++)
            cnt[__ldg(ip + s) >> 9]++;
        int st1 = cnt[0];
        int st2 = st1 + cnt[1];
        int st3 = st2 + cnt[2];
        g_soff[q] = (unsigned)st1 | ((unsigned)st2 << 8) | ((unsigned)st3 << 16);
        int pos[4] = {0, st1, st2, st3};
#pragma unroll
        for (int s = 0; s < USEL; s++) {
            int ki = __ldg(ip + s);
            int c = ki >> 9;
            g_sidx[q * USEL + pos[c]++] = (unsigned short)(ki & (MCH - 1));
        }
    }
}

// ================= 3. M scores: chunked, smem-resident K + smem idx lists =====
// (exact R8 structure — best measured config: 67.6 us)
__global__ __launch_bounds__(1024, 1) void m_kernel(const float* __restrict__ Q,
                                                    const float* __restrict__ K) {
    extern __shared__ float smf[];
    float* Ks = smf;                                         // MCH x 64
    unsigned short* sIdx = (unsigned short*)((char*)smf + MS_IDX);
    unsigned* sOff = (unsigned*)((char*)smf + MS_OFF);

    int t = threadIdx.x, lane = t & 31, warp = t >> 5;
    int g = lane >> 3, h = lane & 7;
    int bh = blockIdx.y;
    int qlo = blockIdx.x * MQT;

    // stage this q-tile's index lists (40 KB) and offsets (2 KB)
    {
        const uint4* src = (const uint4*)(g_sidx + (size_t)qlo * USEL);
        uint4* dst = (uint4*)sIdx;
        for (int f = t; f < (MQT * USEL * 2) / 16; f += 1024)
            dst[f] = __ldg(src + f);
        if (t < MQT) sOff[t] = g_soff[qlo + t];
    }

    const float* Kb = K + (size_t)bh * LSEQ * DIM;
    float mxs = -1e30f, sms = 0.f;

    for (int c = 0; c < LSEQ / MCH; c++) {
        int cb = c * MCH;
        __syncthreads();   // previous chunk fully consumed (also covers idx staging)
#pragma unroll
        for (int k = 0; k < (MCH * 16) / 1024; k++) {
            int f = t + k * 1024;
            ((float4*)Ks)[f] = __ldg((const float4*)(Kb + (size_t)cb * DIM) + f);
        }
        __syncthreads();

        for (int i = 0; i < MQT / 32; i++) {          // 16 queries per warp
            int ql = warp * (MQT / 32) + i;
            int q = qlo + ql;
            unsigned sw = sOff[ql];
            int lo = c ? (int)((sw >> (8 * (c - 1))) & 255u) : 0;
            int hi = (c < 3) ? (int)((sw >> (8 * c)) & 255u) : USEL;

            const unsigned short* sq = sIdx + ql * USEL;
            const float4* Q4 = (const float4*)(Q + ((size_t)bh * LSEQ + q) * DIM);
            float4 qa = __ldg(Q4 + h);
            float4 qb = __ldg(Q4 + h + 8);

            float mxq = -1e30f, smq = 0.f;
#pragma unroll 2
            for (int p0 = lo; p0 < hi; p0 += 4) {
                int p = p0 + g;
                bool act = p < hi;
                int kil = sq[min(p, hi - 1)];    // broadcast LDS.U16
                const float4* Kr = (const float4*)(Ks + (kil << 6));
                float4 a0 = Kr[h], a1 = Kr[h + 8];
                float e0 = qa.x * a0.x;          // two independent chains
                float e1 = qb.x * a1.x;
                e0 = fmaf(qa.y, a0.y, e0);
                e1 = fmaf(qb.y, a1.y, e1);
                e0 = fmaf(qa.z, a0.z, e0);
                e1 = fmaf(qb.z, a1.z, e1);
                e0 = fmaf(qa.w, a0.w, e0);
                e1 = fmaf(qb.w, a1.w, e1);
                float d = e0 + e1;
                d += __shfl_xor_sync(0xFFFFFFFFu, d, 1);
                d += __shfl_xor_sync(0xFFFFFFFFu, d, 2);
                d += __shfl_xor_sync(0xFFFFFFFFu, d, 4);
                if (act) { mxq = fmaxf(mxq, d); smq += d; }
            }
            mxq = fmaxf(mxq, __shfl_xor_sync(0xFFFFFFFFu, mxq, 8));
            mxq = fmaxf(mxq, __shfl_xor_sync(0xFFFFFFFFu, mxq, 16));
            smq += __shfl_xor_sync(0xFFFFFFFFu, smq, 8);
            smq += __shfl_xor_sync(0xFFFFFFFFu, smq, 16);
            if (lane == i) { mxs = fmaxf(mxs, mxq); sms += smq; }
        }
    }

    if (lane < MQT / 32) {
        int q = qlo + warp * (MQT / 32) + lane;
        g_Mkey[bh * LSEQ + q] = f2key(mxs - sms * (1.0f / LSEQ));
    }
}

// ================= 4. top-40 per (b,h) via radix select (512 threads) ========
__global__ __launch_bounds__(512) void topk_kernel() {
    __shared__ unsigned skeys[LSEQ];
    __shared__ unsigned hist[256];
    __shared__ int ebuf[64];
    __shared__ unsigned s_prefix;
    __shared__ int s_remaining, s_cnt, s_eq;

    int bh = blockIdx.x, t = threadIdx.x;
    for (int i = t; i < LSEQ; i += 512)
        skeys[i] = g_Mkey[bh * LSEQ + i];
    if (t == 0) { s_prefix = 0u; s_remaining = USEL; s_cnt = 0; s_eq = 0; }
    __syncthreads();

    const unsigned himask[4] = {0u, 0xFF000000u, 0xFFFF0000u, 0xFFFFFF00u};
#pragma unroll
    for (int r = 0; r < 4; r++) {
        int shift = 24 - 8 * r;
        if (t < 256) hist[t] = 0;
        __syncthreads();
        unsigned pfx = s_prefix;
        for (int i = t; i < LSEQ; i += 512) {
            unsigned k = skeys[i];
            if ((k & himask[r]) == pfx)
                atomicAdd(&hist[(k >> shift) & 255u], 1u);
        }
        __syncthreads();
        if (t < 32) {
            unsigned v[8], tot = 0;
#pragma unroll
            for (int c = 0; c < 8; c++) { v[c] = hist[t * 8 + c]; tot += v[c]; }
            unsigned suf = tot;
#pragma unroll
            for (int off = 1; off < 32; off <<= 1) {
                unsigned o = __shfl_down_sync(0xFFFFFFFFu, suf, off);
                if (t + off < 32) suf += o;
            }
            unsigned below = suf - tot;
            int rem = s_remaining;
#pragma unroll
            for (int c = 7; c >= 0; c--) {
                unsigned here = below + v[c];
                if ((int)here >= rem && (int)below < rem) {
                    s_prefix = pfx | ((unsigned)(t * 8 + c) << shift);
                    s_remaining = rem - (int)below;
                }
                below = here;
            }
        }
        __syncthreads();
    }

    unsigned T = s_prefix;
    int need_eq = s_remaining;

    for (int i = t; i < LSEQ; i += 512) {
        unsigned k = skeys[i];
        if (k > T) {
            int p = atomicAdd(&s_cnt, 1);
            g_topk[bh * USEL + p] = i;
        } else if (k == T) {
            int p = atomicAdd(&s_eq, 1);
            if (p < 64) ebuf[p] = i;
        }
    }
    __syncthreads();

    int cnt_gt = s_cnt, cnt_eq = s_eq;
    if (cnt_eq == need_eq) {
        if (t < cnt_eq)
            g_topk[bh * USEL + cnt_gt + t] = ebuf[t];
    } else if (t == 0) {
        if (cnt_eq <= 64) {
            for (int n = 0; n < need_eq; n++) {
                int bi = -1, bv = LSEQ;
                for (int j = 0; j < cnt_eq; j++)
                    if (ebuf[j] < bv) { bv = ebuf[j]; bi = j; }
                g_topk[bh * USEL + cnt_gt + n] = bv;
                ebuf[bi] = LSEQ;
            }
        } else {
            int n = 0;
            for (int i = 0; i < LSEQ && n < need_eq; i++)
                if (skeys[i] == T) g_topk[bh * USEL + cnt_gt + n++] = i;
        }
    }
}

// ================= 5. attention partials: one 64-key tile per block ==========
// (R8's best measured config: NCH=32, plain per-tile softmax in registers)
__global__ __launch_bounds__(256) void attn_kernel(const float* __restrict__ Q,
                                                   const float* __restrict__ K,
                                                   const float* __restrict__ V) {
    extern __shared__ float sm[];
    float* Qs = sm + A_QS;
    float* Ks = sm + A_KS;
    float* Vs = sm + A_VS;
    float* Pt = sm + A_PT;

    int ch = blockIdx.x, bh = blockIdx.y;
    int t = threadIdx.x;
    int i = t >> 5, j = t & 31;
    int kb = ch * CHK;

    const float* Kb = K + (size_t)bh * LSEQ * DIM;
    const float* Vb = V + (size_t)bh * LSEQ * DIM;

    for (int e = t; e < USEL * DIM; e += 256) {
        int q = e >> 6, d = e & 63;
        int qi = g_topk[bh * USEL + q];
        Qs[e] = Q[((size_t)bh * LSEQ + qi) * DIM + d] * 0.125f;
    }
#pragma unroll
    for (int rr = 0; rr < 4; rr++) {
        int f = t + rr * 256;
        int r = f >> 4, c4 = f & 15;
        *(float4*)&Ks[r * KVS + c4 * 4] =
            __ldg((const float4*)(Kb + (size_t)(kb + r) * DIM) + c4);
        *(float4*)&Vs[r * KVS + c4 * 4] =
            __ldg((const float4*)(Vb + (size_t)(kb + r) * DIM) + c4);
    }
    __syncthreads();

    float s0[5], s1[5];
#pragma unroll
    for (int a = 0; a < 5; a++) { s0[a] = 0.f; s1[a] = 0.f; }
#pragma unroll
    for (int d4 = 0; d4 < 16; d4++) {
        float4 k0 = *(const float4*)&Ks[j * KVS + d4 * 4];
        float4 k1 = *(const float4*)&Ks[(j + 32) * KVS + d4 * 4];
#pragma unroll
        for (int a = 0; a < 5; a++) {
            float4 qv = *(const float4*)&Qs[(i + 8 * a) * 64 + d4 * 4];
            float u0 = s0[a];
            u0 = fmaf(qv.x, k0.x, u0);
            u0 = fmaf(qv.y, k0.y, u0);
            u0 = fmaf(qv.z, k0.z, u0);
            u0 = fmaf(qv.w, k0.w, u0);
            s0[a] = u0;
            float u1 = s1[a];
            u1 = fmaf(qv.x, k1.x, u1);
            u1 = fmaf(qv.y, k1.y, u1);
            u1 = fmaf(qv.z, k1.z, u1);
            u1 = fmaf(qv.w, k1.w, u1);
            s1[a] = u1;
        }
    }

    float m_[5], l_[5], acc[5][2];
#pragma unroll
    for (int a = 0; a < 5; a++) {
        float tm = fmaxf(s0[a], s1[a]);
#pragma unroll
        for (int o = 16; o; o >>= 1)
            tm = fmaxf(tm, __shfl_xor_sync(0xFFFFFFFFu, tm, o));
        float p0 = __expf(s0[a] - tm);
        float p1 = __expf(s1[a] - tm);
        float su = p0 + p1;
#pragma unroll
        for (int o = 16; o; o >>= 1)
            su += __shfl_xor_sync(0xFFFFFFFFu, su, o);
        m_[a] = tm;
        l_[a] = su;
        acc[a][0] = 0.f;
        acc[a][1] = 0.f;
        Pt[(i * 5 + a) * 64 + j]      = p0;
        Pt[(i * 5 + a) * 64 + j + 32] = p1;
    }
    __syncwarp();

#pragma unroll
    for (int k4 = 0; k4 < 16; k4++) {
        int k = k4 * 4;
        float v00 = Vs[(k + 0) * KVS + j];
        float v01 = Vs[(k + 1) * KVS + j];
        float v02 = Vs[(k + 2) * KVS + j];
        float v03 = Vs[(k + 3) * KVS + j];
        float v10 = Vs[(k + 0) * KVS + j + 32];
        float v11 = Vs[(k + 1) * KVS + j + 32];
        float v12 = Vs[(k + 2) * KVS + j + 32];
        float v13 = Vs[(k + 3) * KVS + j + 32];
#pragma unroll
        for (int a = 0; a < 5; a++) {
            float4 p = *(const float4*)&Pt[(i * 5 + a) * 64 + k];
            float u0 = acc[a][0];
            u0 = fmaf(p.x, v00, u0);
            u0 = fmaf(p.y, v01, u0);
            u0 = fmaf(p.z, v02, u0);
            u0 = fmaf(p.w, v03, u0);
            acc[a][0] = u0;
            float u1 = acc[a][1];
            u1 = fmaf(p.x, v10, u1);
            u1 = fmaf(p.y, v11, u1);
            u1 = fmaf(p.z, v12, u1);
            u1 = fmaf(p.w, v13, u1);
            acc[a][1] = u1;
        }
    }

    float* pa = g_pacc + (size_t)(bh * NCH + ch) * USEL * DIM;
#pragma unroll
    for (int a = 0; a < 5; a++) {
        int q = i + 8 * a;
        pa[q * DIM + j]      = acc[a][0];
        pa[q * DIM + j + 32] = acc[a][1];
    }
    if (j == 0) {
#pragma unroll
        for (int a = 0; a < 5; a++) {
            g_pm[(bh * NCH + ch) * USEL + i + 8 * a] = m_[a];
            g_pl[(bh * NCH + ch) * USEL + i + 8 * a] = l_[a];
        }
    }
}

// ================= 6. merge partials, scatter into output =================
__global__ void merge_kernel(float* __restrict__ out) {
    int u = blockIdx.x, bh = blockIdx.y, d = threadIdx.x;
    float M = -1e30f;
#pragma unroll
    for (int c = 0; c < NCH; c++)
        M = fmaxf(M, g_pm[(bh * NCH + c) * USEL + u]);
    float L = 0.f, o = 0.f;
#pragma unroll
    for (int c = 0; c < NCH; c++) {
        float w = __expf(g_pm[(bh * NCH + c) * USEL + u] - M);
        L += g_pl[(bh * NCH + c) * USEL + u] * w;
        o = fmaf(g_pacc[((size_t)(bh * NCH + c) * USEL + u) * DIM + d], w, o);
    }
    int qi = g_topk[bh * USEL + u];
    out[((size_t)bh * LSEQ + qi) * DIM + d] = o / L;
}

// ================= launcher =================
extern "C" void kernel_launch(void* const* d_in, const int* in_sizes, int n_in,
                              void* d_out, int out_size) {
    const float* Q    = (const float*)d_in[0];
    const float* K    = (const float*)d_in[1];
    const float* V    = (const float*)d_in[2];
    const int*   idxs = (const int*)d_in[3];
    float* out = (float*)d_out;
    int u = in_sizes[3] / LSEQ;   // 40

    cudaFuncSetAttribute(m_kernel, cudaFuncAttributeMaxDynamicSharedMemorySize, M_SMEM);
    cudaFuncSetAttribute(attn_kernel, cudaFuncAttributeMaxDynamicSharedMemorySize, A_SMEM);

    prep_kernel<<<34, 1024>>>(V, idxs, (float4*)out, u);
    m_kernel<<<dim3(LSEQ / MQT, BH), 1024, M_SMEM>>>(Q, K);
    topk_kernel<<<BH, 512>>>();
    attn_kernel<<<dim3(NCH, BH), 256, A_SMEM>>>(Q, K, V);
    merge_kernel<<<dim3(USEL, BH), 64>>>(out);
}

// round 13
// speedup vs baseline: 1.0248x; 1.0248x over previous
#include <cuda_runtime.h>
#include <cuda_bf16.h>
#include <math.h>

// Problem constants (fixed bench shapes)
#define BH    32            // B*H = 4*8
#define LSEQ  2048          // sequence length
#define DIM   64            // head dim
#define USEL  40            // u = U_part
#define NCH   32            // key chunks for split-softmax attention
#define CHK   (LSEQ/NCH)    // 64 keys per chunk (single tile per block)
#define KVS   68            // padded smem row stride for attn K/V tiles
#define MCH   512           // m_kernel key-chunk size
#define MQT   512           // m_kernel q-tile (4 tiles x 32 bh = 128 blocks, 1 wave)

// m_kernel smem layout (bytes) — exact R8 layout (best measured: 67.6 us)
#define MS_K     0                                   // 512*64*4   = 131072
#define MS_IDX   (MCH * DIM * 4)                     // +512*40*2  =  40960
#define MS_OFF   (MS_IDX + MQT * USEL * 2)           // +512*4     =   2048
#define M_SMEM   (MS_OFF + MQT * 4)                  // 174080 B (170 KB)

#define A_QS    0
#define A_KS    (USEL * DIM)
#define A_VS    (A_KS + 64 * KVS)
#define A_PT    (A_VS + 64 * KVS)
#define A_SMEM  ((A_PT + 8 * 5 * 64) * 4)            // 55,296 B

// -------- scratch (device globals; no allocation allowed) --------
__device__ unsigned g_Mkey[BH * LSEQ];
__device__ int   g_topk[BH * USEL];
__device__ float g_meanV[BH * DIM];
__device__ float g_pm[BH * NCH * USEL];
__device__ float g_pl[BH * NCH * USEL];
__device__ float g_pacc[(size_t)BH * NCH * USEL * DIM];   // 10.5 MB
__device__ unsigned short g_sidx[LSEQ * USEL];      // chunk-sorted, PRE-MASKED local idx
__device__ unsigned g_soff[LSEQ];                   // packed chunk start offsets
__device__ int   g_syncM[BH];                       // m-block arrival counters (self-reset)
__device__ int   g_syncA[BH];                       // attn-block arrival counters (self-reset)

__device__ __forceinline__ unsigned f2key(float x) {
    unsigned k = __float_as_uint(x);
    return (k & 0x80000000u) ? ~k : (k | 0x80000000u);
}

// ================= 1. mean of V per (b,h): vectorized (R8) =================
__global__ __launch_bounds__(1024) void mean_kernel(const float* __restrict__ V) {
    __shared__ float4 sb[64][16];
    int bh = blockIdx.x, t = threadIdx.x;
    int part = t >> 4, c4 = t & 15;
    const float4* Vb = (const float4*)(V + (size_t)bh * LSEQ * DIM);
    float4 s = make_float4(0.f, 0.f, 0.f, 0.f);
    for (int l = part; l < LSEQ; l += 64) {
        float4 v = __ldg(Vb + l * 16 + c4);
        s.x += v.x; s.y += v.y; s.z += v.z; s.w += v.w;
    }
    sb[part][c4] = s;
    __syncthreads();
#pragma unroll
    for (int o = 32; o; o >>= 1) {
        if (part < o) {
            float4 a = sb[part][c4], b = sb[part + o][c4];
            a.x += b.x; a.y += b.y; a.z += b.z; a.w += b.w;
            sb[part][c4] = a;
        }
        __syncthreads();
    }
    if (t < 16) {
        float4 a = sb[0][t];
        a.x *= (1.0f / LSEQ); a.y *= (1.0f / LSEQ);
        a.z *= (1.0f / LSEQ); a.w *= (1.0f / LSEQ);
        ((float4*)g_meanV)[bh * 16 + t] = a;
    }
}

// ================= 2. broadcast-fill output with meanV (R8, chip-wide) =======
__global__ void fill_kernel(float4* __restrict__ out) {
    int i = blockIdx.x * blockDim.x + threadIdx.x;
    int bh = i >> 15;
    int d4 = i & 15;
    out[i] = ((const float4*)g_meanV)[bh * 16 + d4];
}

// ================= 2b. bucket samples by key-chunk; store LOCAL idx (R8) =====
__global__ void sort_kernel(const int* __restrict__ idxs, int u) {
    int q = blockIdx.x * blockDim.x + threadIdx.x;
    if (q >= LSEQ) return;
    const int* ip = idxs + (size_t)q * u;
    int cnt[4] = {0, 0, 0, 0};
#pragma unroll
    for (int s = 0; s < USEL; s++)
        cnt[__ldg(ip + s) >> 9]++;
    int st1 = cnt[0];
    int st2 = st1 + cnt[1];
    int st3 = st2 + cnt[2];
    g_soff[q] = (unsigned)st1 | ((unsigned)st2 << 8) | ((unsigned)st3 << 16);
    int pos[4] = {0, st1, st2, st3};
#pragma unroll
    for (int s = 0; s < USEL; s++) {
        int ki = __ldg(ip + s);
        int c = ki >> 9;
        g_sidx[q * USEL + pos[c]++] = (unsigned short)(ki & (MCH - 1));
    }
}

// ================= 3. M scores (R8) + fused per-bh top-40 radix tail ==========
__global__ __launch_bounds__(1024, 1) void m_kernel(const float* __restrict__ Q,
                                                    const float* __restrict__ K) {
    extern __shared__ float smf[];
    float* Ks = smf;                                         // MCH x 64
    unsigned short* sIdx = (unsigned short*)((char*)smf + MS_IDX);
    unsigned* sOff = (unsigned*)((char*)smf + MS_OFF);

    __shared__ int s_last;
    __shared__ unsigned s_prefix;
    __shared__ int s_remaining, s_cnt, s_eq;
    __shared__ int ebuf[64];

    int t = threadIdx.x, lane = t & 31, warp = t >> 5;
    int g = lane >> 3, h = lane & 7;
    int bh = blockIdx.y;
    int qlo = blockIdx.x * MQT;

    // stage this q-tile's index lists (40 KB) and offsets (2 KB)
    {
        const uint4* src = (const uint4*)(g_sidx + (size_t)qlo * USEL);
        uint4* dst = (uint4*)sIdx;
        for (int f = t; f < (MQT * USEL * 2) / 16; f += 1024)
            dst[f] = __ldg(src + f);
        if (t < MQT) sOff[t] = g_soff[qlo + t];
    }

    const float* Kb = K + (size_t)bh * LSEQ * DIM;
    float mxs = -1e30f, sms = 0.f;

    for (int c = 0; c < LSEQ / MCH; c++) {
        int cb = c * MCH;
        __syncthreads();   // previous chunk fully consumed (also covers idx staging)
#pragma unroll
        for (int k = 0; k < (MCH * 16) / 1024; k++) {
            int f = t + k * 1024;
            ((float4*)Ks)[f] = __ldg((const float4*)(Kb + (size_t)cb * DIM) + f);
        }
        __syncthreads();

        for (int i = 0; i < MQT / 32; i++) {          // 16 queries per warp
            int ql = warp * (MQT / 32) + i;
            int q = qlo + ql;
            unsigned sw = sOff[ql];
            int lo = c ? (int)((sw >> (8 * (c - 1))) & 255u) : 0;
            int hi = (c < 3) ? (int)((sw >> (8 * c)) & 255u) : USEL;

            const unsigned short* sq = sIdx + ql * USEL;
            const float4* Q4 = (const float4*)(Q + ((size_t)bh * LSEQ + q) * DIM);
            float4 qa = __ldg(Q4 + h);
            float4 qb = __ldg(Q4 + h + 8);

            float mxq = -1e30f, smq = 0.f;
#pragma unroll 2
            for (int p0 = lo; p0 < hi; p0 += 4) {
                int p = p0 + g;
                bool act = p < hi;
                int kil = sq[min(p, hi - 1)];    // broadcast LDS.U16
                const float4* Kr = (const float4*)(Ks + (kil << 6));
                float4 a0 = Kr[h], a1 = Kr[h + 8];
                float e0 = qa.x * a0.x;          // two independent chains
                float e1 = qb.x * a1.x;
                e0 = fmaf(qa.y, a0.y, e0);
                e1 = fmaf(qb.y, a1.y, e1);
                e0 = fmaf(qa.z, a0.z, e0);
                e1 = fmaf(qb.z, a1.z, e1);
                e0 = fmaf(qa.w, a0.w, e0);
                e1 = fmaf(qb.w, a1.w, e1);
                float d = e0 + e1;
                d += __shfl_xor_sync(0xFFFFFFFFu, d, 1);
                d += __shfl_xor_sync(0xFFFFFFFFu, d, 2);
                d += __shfl_xor_sync(0xFFFFFFFFu, d, 4);
                if (act) { mxq = fmaxf(mxq, d); smq += d; }
            }
            mxq = fmaxf(mxq, __shfl_xor_sync(0xFFFFFFFFu, mxq, 8));
            mxq = fmaxf(mxq, __shfl_xor_sync(0xFFFFFFFFu, mxq, 16));
            smq += __shfl_xor_sync(0xFFFFFFFFu, smq, 8);
            smq += __shfl_xor_sync(0xFFFFFFFFu, smq, 16);
            if (lane == i) { mxs = fmaxf(mxs, mxq); sms += smq; }
        }
    }

    if (lane < MQT / 32) {
        int q = qlo + warp * (MQT / 32) + lane;
        g_Mkey[bh * LSEQ + q] = f2key(mxs - sms * (1.0f / LSEQ));
    }

    // ---------- tail: last q-tile block for this bh runs the radix select ----
    __threadfence();                     // publish g_Mkey writes
    __syncthreads();
    if (t == 0)
        s_last = (atomicAdd(&g_syncM[bh], 1) == (LSEQ / MQT) - 1);
    __syncthreads();
    if (!s_last) return;
    __threadfence();                     // acquire other blocks' g_Mkey writes

    unsigned* skeys = (unsigned*)smf;    // reuse Ks region: 8 KB
    unsigned* hist  = (unsigned*)smf + LSEQ;
    for (int i = t; i < LSEQ; i += 1024)
        skeys[i] = g_Mkey[bh * LSEQ + i];
    if (t == 0) {
        s_prefix = 0u; s_remaining = USEL; s_cnt = 0; s_eq = 0;
        g_syncM[bh] = 0;                 // self-reset for next graph replay
    }
    __syncthreads();

    const unsigned himask[4] = {0u, 0xFF000000u, 0xFFFF0000u, 0xFFFFFF00u};
#pragma unroll
    for (int r = 0; r < 4; r++) {
        int shift = 24 - 8 * r;
        if (t < 256) hist[t] = 0;
        __syncthreads();
        unsigned pfx = s_prefix;
        for (int i = t; i < LSEQ; i += 1024) {
            unsigned k = skeys[i];
            if ((k & himask[r]) == pfx)
                atomicAdd(&hist[(k >> shift) & 255u], 1u);
        }
        __syncthreads();
        if (t < 32) {
            unsigned v[8], tot = 0;
#pragma unroll
            for (int c = 0; c < 8; c++) { v[c] = hist[t * 8 + c]; tot += v[c]; }
            unsigned suf = tot;
#pragma unroll
            for (int off = 1; off < 32; off <<= 1) {
                unsigned o = __shfl_down_sync(0xFFFFFFFFu, suf, off);
                if (t + off < 32) suf += o;
            }
            unsigned below = suf - tot;
            int rem = s_remaining;
#pragma unroll
            for (int c = 7; c >= 0; c--) {
                unsigned here = below + v[c];
                if ((int)here >= rem && (int)below < rem) {
                    s_prefix = pfx | ((unsigned)(t * 8 + c) << shift);
                    s_remaining = rem - (int)below;
                }
                below = here;
            }
        }
        __syncthreads();
    }

    unsigned T = s_prefix;
    int need_eq = s_remaining;

    for (int i = t; i < LSEQ; i += 1024) {
        unsigned k = skeys[i];
        if (k > T) {
            int p = atomicAdd(&s_cnt, 1);
            g_topk[bh * USEL + p] = i;
        } else if (k == T) {
            int p = atomicAdd(&s_eq, 1);
            if (p < 64) ebuf[p] = i;
        }
    }
    __syncthreads();

    int cnt_gt = s_cnt, cnt_eq = s_eq;
    if (cnt_eq == need_eq) {
        if (t < cnt_eq)
            g_topk[bh * USEL + cnt_gt + t] = ebuf[t];
    } else if (t == 0) {
        if (cnt_eq <= 64) {
            for (int n = 0; n < need_eq; n++) {
                int bi = -1, bv = LSEQ;
                for (int j2 = 0; j2 < cnt_eq; j2++)
                    if (ebuf[j2] < bv) { bv = ebuf[j2]; bi = j2; }
                g_topk[bh * USEL + cnt_gt + n] = bv;
                ebuf[bi] = LSEQ;
            }
        } else {
            int n = 0;
            for (int i = 0; i < LSEQ && n < need_eq; i++)
                if (skeys[i] == T) g_topk[bh * USEL + cnt_gt + n++] = i;
        }
    }
}

// ================= 5. attention partials (R8) + fused per-bh merge tail ======
__global__ __launch_bounds__(256) void attn_kernel(const float* __restrict__ Q,
                                                   const float* __restrict__ K,
                                                   const float* __restrict__ V,
                                                   float* __restrict__ out) {
    extern __shared__ float sm[];
    float* Qs = sm + A_QS;
    float* Ks = sm + A_KS;
    float* Vs = sm + A_VS;
    float* Pt = sm + A_PT;
    __shared__ int s_last;

    int ch = blockIdx.x, bh = blockIdx.y;
    int t = threadIdx.x;
    int i = t >> 5, j = t & 31;
    int kb = ch * CHK;

    const float* Kb = K + (size_t)bh * LSEQ * DIM;
    const float* Vb = V + (size_t)bh * LSEQ * DIM;

    for (int e = t; e < USEL * DIM; e += 256) {
        int q = e >> 6, d = e & 63;
        int qi = g_topk[bh * USEL + q];
        Qs[e] = Q[((size_t)bh * LSEQ + qi) * DIM + d] * 0.125f;
    }
#pragma unroll
    for (int rr = 0; rr < 4; rr++) {
        int f = t + rr * 256;
        int r = f >> 4, c4 = f & 15;
        *(float4*)&Ks[r * KVS + c4 * 4] =
            __ldg((const float4*)(Kb + (size_t)(kb + r) * DIM) + c4);
        *(float4*)&Vs[r * KVS + c4 * 4] =
            __ldg((const float4*)(Vb + (size_t)(kb + r) * DIM) + c4);
    }
    __syncthreads();

    float s0[5], s1[5];
#pragma unroll
    for (int a = 0; a < 5; a++) { s0[a] = 0.f; s1[a] = 0.f; }
#pragma unroll
    for (int d4 = 0; d4 < 16; d4++) {
        float4 k0 = *(const float4*)&Ks[j * KVS + d4 * 4];
        float4 k1 = *(const float4*)&Ks[(j + 32) * KVS + d4 * 4];
#pragma unroll
        for (int a = 0; a < 5; a++) {
            float4 qv = *(const float4*)&Qs[(i + 8 * a) * 64 + d4 * 4];
            float u0 = s0[a];
            u0 = fmaf(qv.x, k0.x, u0);
            u0 = fmaf(qv.y, k0.y, u0);
            u0 = fmaf(qv.z, k0.z, u0);
            u0 = fmaf(qv.w, k0.w, u0);
            s0[a] = u0;
            float u1 = s1[a];
            u1 = fmaf(qv.x, k1.x, u1);
            u1 = fmaf(qv.y, k1.y, u1);
            u1 = fmaf(qv.z, k1.z, u1);
            u1 = fmaf(qv.w, k1.w, u1);
            s1[a] = u1;
        }
    }

    float m_[5], l_[5], acc[5][2];
#pragma unroll
    for (int a = 0; a < 5; a++) {
        float tm = fmaxf(s0[a], s1[a]);
#pragma unroll
        for (int o = 16; o; o >>= 1)
            tm = fmaxf(tm, __shfl_xor_sync(0xFFFFFFFFu, tm, o));
        float p0 = __expf(s0[a] - tm);
        float p1 = __expf(s1[a] - tm);
        float su = p0 + p1;
#pragma unroll
        for (int o = 16; o; o >>= 1)
            su += __shfl_xor_sync(0xFFFFFFFFu, su, o);
        m_[a] = tm;
        l_[a] = su;
        acc[a][0] = 0.f;
        acc[a][1] = 0.f;
        Pt[(i * 5 + a) * 64 + j]      = p0;
        Pt[(i * 5 + a) * 64 + j + 32] = p1;
    }
    __syncwarp();

#pragma unroll
    for (int k4 = 0; k4 < 16; k4++) {
        int k = k4 * 4;
        float v00 = Vs[(k + 0) * KVS + j];
        float v01 = Vs[(k + 1) * KVS + j];
        float v02 = Vs[(k + 2) * KVS + j];
        float v03 = Vs[(k + 3) * KVS + j];
        float v10 = Vs[(k + 0) * KVS + j + 32];
        float v11 = Vs[(k + 1) * KVS + j + 32];
        float v12 = Vs[(k + 2) * KVS + j + 32];
        float v13 = Vs[(k + 3) * KVS + j + 32];
#pragma unroll
        for (int a = 0; a < 5; a++) {
            float4 p = *(const float4*)&Pt[(i * 5 + a) * 64 + k];
            float u0 = acc[a][0];
            u0 = fmaf(p.x, v00, u0);
            u0 = fmaf(p.y, v01, u0);
            u0 = fmaf(p.z, v02, u0);
            u0 = fmaf(p.w, v03, u0);
            acc[a][0] = u0;
            float u1 = acc[a][1];
            u1 = fmaf(p.x, v10, u1);
            u1 = fmaf(p.y, v11, u1);
            u1 = fmaf(p.z, v12, u1);
            u1 = fmaf(p.w, v13, u1);
            acc[a][1] = u1;
        }
    }

    float* pa = g_pacc + (size_t)(bh * NCH + ch) * USEL * DIM;
#pragma unroll
    for (int a = 0; a < 5; a++) {
        int q = i + 8 * a;
        pa[q * DIM + j]      = acc[a][0];
        pa[q * DIM + j + 32] = acc[a][1];
    }
    if (j == 0) {
#pragma unroll
        for (int a = 0; a < 5; a++) {
            g_pm[(bh * NCH + ch) * USEL + i + 8 * a] = m_[a];
            g_pl[(bh * NCH + ch) * USEL + i + 8 * a] = l_[a];
        }
    }

    // ---------- tail: last chunk block for this bh merges + scatters ---------
    __threadfence();                     // publish g_pacc / g_pm / g_pl
    __syncthreads();
    if (t == 0)
        s_last = (atomicAdd(&g_syncA[bh], 1) == NCH - 1);
    __syncthreads();
    if (!s_last) return;
    __threadfence();                     // acquire other blocks' partials
    if (t == 0) g_syncA[bh] = 0;         // self-reset for next graph replay

    const float* pmb = g_pm + bh * NCH * USEL;
    const float* plb = g_pl + bh * NCH * USEL;
    for (int e = t; e < USEL * DIM; e += 256) {
        int u = e >> 6, d = e & 63;
        float M = -1e30f;
#pragma unroll
        for (int c = 0; c < NCH; c++)
            M = fmaxf(M, pmb[c * USEL + u]);
        float L = 0.f, o = 0.f;
#pragma unroll
        for (int c = 0; c < NCH; c++) {
            float w = __expf(pmb[c * USEL + u] - M);
            L += plb[c * USEL + u] * w;
            o = fmaf(g_pacc[((size_t)(bh * NCH + c) * USEL + u) * DIM + d], w, o);
        }
        int qi = g_topk[bh * USEL + u];
        out[((size_t)bh * LSEQ + qi) * DIM + d] = o / L;
    }
}

// ================= launcher =================
extern "C" void kernel_launch(void* const* d_in, const int* in_sizes, int n_in,
                              void* d_out, int out_size) {
    const float* Q    = (const float*)d_in[0];
    const float* K    = (const float*)d_in[1];
    const float* V    = (const float*)d_in[2];
    const int*   idxs = (const int*)d_in[3];
    float* out = (float*)d_out;
    int u = in_sizes[3] / LSEQ;   // 40

    cudaFuncSetAttribute(m_kernel, cudaFuncAttributeMaxDynamicSharedMemorySize, M_SMEM);
    cudaFuncSetAttribute(attn_kernel, cudaFuncAttributeMaxDynamicSharedMemorySize, A_SMEM);

    mean_kernel<<<BH, 1024>>>(V);
    fill_kernel<<<(BH * LSEQ * 16) / 256, 256>>>((float4*)out);
    sort_kernel<<<LSEQ / 256, 256>>>(idxs, u);
    m_kernel<<<dim3(LSEQ / MQT, BH), 1024, M_SMEM>>>(Q, K);
    attn_kernel<<<dim3(NCH, BH), 256, A_SMEM>>>(Q, K, V, out);
}

// round 14
// speedup vs baseline: 1.2252x; 1.1955x over previous
#include <cuda_runtime.h>
#include <cuda_bf16.h>
#include <math.h>

// Problem constants (fixed bench shapes)
#define BH    32            // B*H = 4*8
#define LSEQ  2048          // sequence length
#define DIM   64            // head dim
#define USEL  40            // u = U_part
#define NCH   32            // key chunks for split-softmax attention
#define CHK   (LSEQ/NCH)    // 64 keys per chunk (single tile per block)
#define KVS   68            // padded smem row stride for attn K/V tiles
#define MCH   512           // m_kernel key-chunk size
#define MQT   512           // m_kernel q-tile (4 tiles x 32 bh = 128 blocks, 1 wave)

// m_kernel smem layout (bytes) — exact R8 layout
#define MS_K     0                                   // 512*64*4   = 131072
#define MS_IDX   (MCH * DIM * 4)                     // +512*40*2  =  40960
#define MS_OFF   (MS_IDX + MQT * USEL * 2)           // +512*4     =   2048
#define M_SMEM   (MS_OFF + MQT * 4)                  // 174080 B (170 KB)

#define A_QS    0
#define A_KS    (USEL * DIM)
#define A_VS    (A_KS + 64 * KVS)
#define A_PT    (A_VS + 64 * KVS)
#define A_SMEM  ((A_PT + 8 * 5 * 64) * 4)            // 55,296 B

// -------- scratch (device globals; no allocation allowed) --------
__device__ unsigned g_Mkey[BH * LSEQ];
__device__ int   g_topk[BH * USEL];
__device__ float g_meanV[BH * DIM];
__device__ float g_pm[BH * NCH * USEL];
__device__ float g_pl[BH * NCH * USEL];
__device__ float g_pacc[(size_t)BH * NCH * USEL * DIM];   // 10.5 MB
__device__ unsigned short g_sidx[LSEQ * USEL];      // chunk-sorted, PRE-MASKED local idx
__device__ unsigned g_soff[LSEQ];                   // packed chunk start offsets
__device__ int   g_syncM[BH];                       // m-block arrival counters (self-reset)

__device__ __forceinline__ unsigned f2key(float x) {
    unsigned k = __float_as_uint(x);
    return (k & 0x80000000u) ? ~k : (k | 0x80000000u);
}

// ================= 1. mean of V per (b,h): vectorized (R8) =================
__global__ __launch_bounds__(1024) void mean_kernel(const float* __restrict__ V) {
    __shared__ float4 sb[64][16];
    int bh = blockIdx.x, t = threadIdx.x;
    int part = t >> 4, c4 = t & 15;
    const float4* Vb = (const float4*)(V + (size_t)bh * LSEQ * DIM);
    float4 s = make_float4(0.f, 0.f, 0.f, 0.f);
    for (int l = part; l < LSEQ; l += 64) {
        float4 v = __ldg(Vb + l * 16 + c4);
        s.x += v.x; s.y += v.y; s.z += v.z; s.w += v.w;
    }
    sb[part][c4] = s;
    __syncthreads();
#pragma unroll
    for (int o = 32; o; o >>= 1) {
        if (part < o) {
            float4 a = sb[part][c4], b = sb[part + o][c4];
            a.x += b.x; a.y += b.y; a.z += b.z; a.w += b.w;
            sb[part][c4] = a;
        }
        __syncthreads();
    }
    if (t < 16) {
        float4 a = sb[0][t];
        a.x *= (1.0f / LSEQ); a.y *= (1.0f / LSEQ);
        a.z *= (1.0f / LSEQ); a.w *= (1.0f / LSEQ);
        ((float4*)g_meanV)[bh * 16 + t] = a;
    }
}

// ================= 2. broadcast-fill output with meanV (chip-wide, R8) =======
__global__ void fill_kernel(float4* __restrict__ out) {
    int i = blockIdx.x * blockDim.x + threadIdx.x;
    int bh = i >> 15;
    int d4 = i & 15;
    out[i] = ((const float4*)g_meanV)[bh * 16 + d4];
}

// ================= 2b. bucket samples by key-chunk; store LOCAL idx (R8) =====
__global__ void sort_kernel(const int* __restrict__ idxs, int u) {
    int q = blockIdx.x * blockDim.x + threadIdx.x;
    if (q >= LSEQ) return;
    const int* ip = idxs + (size_t)q * u;
    int cnt[4] = {0, 0, 0, 0};
#pragma unroll
    for (int s = 0; s < USEL; s++)
        cnt[__ldg(ip + s) >> 9]++;
    int st1 = cnt[0];
    int st2 = st1 + cnt[1];
    int st3 = st2 + cnt[2];
    g_soff[q] = (unsigned)st1 | ((unsigned)st2 << 8) | ((unsigned)st3 << 16);
    int pos[4] = {0, st1, st2, st3};
#pragma unroll
    for (int s = 0; s < USEL; s++) {
        int ki = __ldg(ip + s);
        int c = ki >> 9;
        g_sidx[q * USEL + pos[c]++] = (unsigned short)(ki & (MCH - 1));
    }
}

// ================= 3. M scores (R8) + fused per-bh top-40 radix tail (R13) ===
// Tail is compute-light (8 KB of reads) — legal tail fusion.
__global__ __launch_bounds__(1024, 1) void m_kernel(const float* __restrict__ Q,
                                                    const float* __restrict__ K) {
    extern __shared__ float smf[];
    float* Ks = smf;                                         // MCH x 64
    unsigned short* sIdx = (unsigned short*)((char*)smf + MS_IDX);
    unsigned* sOff = (unsigned*)((char*)smf + MS_OFF);

    __shared__ int s_last;
    __shared__ unsigned s_prefix;
    __shared__ int s_remaining, s_cnt, s_eq;
    __shared__ int ebuf[64];

    int t = threadIdx.x, lane = t & 31, warp = t >> 5;
    int g = lane >> 3, h = lane & 7;
    int bh = blockIdx.y;
    int qlo = blockIdx.x * MQT;

    // stage this q-tile's index lists (40 KB) and offsets (2 KB)
    {
        const uint4* src = (const uint4*)(g_sidx + (size_t)qlo * USEL);
        uint4* dst = (uint4*)sIdx;
        for (int f = t; f < (MQT * USEL * 2) / 16; f += 1024)
            dst[f] = __ldg(src + f);
        if (t < MQT) sOff[t] = g_soff[qlo + t];
    }

    const float* Kb = K + (size_t)bh * LSEQ * DIM;
    float mxs = -1e30f, sms = 0.f;

    for (int c = 0; c < LSEQ / MCH; c++) {
        int cb = c * MCH;
        __syncthreads();   // previous chunk fully consumed (also covers idx staging)
#pragma unroll
        for (int k = 0; k < (MCH * 16) / 1024; k++) {
            int f = t + k * 1024;
            ((float4*)Ks)[f] = __ldg((const float4*)(Kb + (size_t)cb * DIM) + f);
        }
        __syncthreads();

        for (int i = 0; i < MQT / 32; i++) {          // 16 queries per warp
            int ql = warp * (MQT / 32) + i;
            int q = qlo + ql;
            unsigned sw = sOff[ql];
            int lo = c ? (int)((sw >> (8 * (c - 1))) & 255u) : 0;
            int hi = (c < 3) ? (int)((sw >> (8 * c)) & 255u) : USEL;

            const unsigned short* sq = sIdx + ql * USEL;
            const float4* Q4 = (const float4*)(Q + ((size_t)bh * LSEQ + q) * DIM);
            float4 qa = __ldg(Q4 + h);
            float4 qb = __ldg(Q4 + h + 8);

            float mxq = -1e30f, smq = 0.f;
#pragma unroll 2
            for (int p0 = lo; p0 < hi; p0 += 4) {
                int p = p0 + g;
                bool act = p < hi;
                int kil = sq[min(p, hi - 1)];    // broadcast LDS.U16
                const float4* Kr = (const float4*)(Ks + (kil << 6));
                float4 a0 = Kr[h], a1 = Kr[h + 8];
                float e0 = qa.x * a0.x;          // two independent chains
                float e1 = qb.x * a1.x;
                e0 = fmaf(qa.y, a0.y, e0);
                e1 = fmaf(qb.y, a1.y, e1);
                e0 = fmaf(qa.z, a0.z, e0);
                e1 = fmaf(qb.z, a1.z, e1);
                e0 = fmaf(qa.w, a0.w, e0);
                e1 = fmaf(qb.w, a1.w, e1);
                float d = e0 + e1;
                d += __shfl_xor_sync(0xFFFFFFFFu, d, 1);
                d += __shfl_xor_sync(0xFFFFFFFFu, d, 2);
                d += __shfl_xor_sync(0xFFFFFFFFu, d, 4);
                if (act) { mxq = fmaxf(mxq, d); smq += d; }
            }
            mxq = fmaxf(mxq, __shfl_xor_sync(0xFFFFFFFFu, mxq, 8));
            mxq = fmaxf(mxq, __shfl_xor_sync(0xFFFFFFFFu, mxq, 16));
            smq += __shfl_xor_sync(0xFFFFFFFFu, smq, 8);
            smq += __shfl_xor_sync(0xFFFFFFFFu, smq, 16);
            if (lane == i) { mxs = fmaxf(mxs, mxq); sms += smq; }
        }
    }

    if (lane < MQT / 32) {
        int q = qlo + warp * (MQT / 32) + lane;
        g_Mkey[bh * LSEQ + q] = f2key(mxs - sms * (1.0f / LSEQ));
    }

    // ---------- tail: last q-tile block for this bh runs the radix select ----
    __threadfence();                     // publish g_Mkey writes
    __syncthreads();
    if (t == 0)
        s_last = (atomicAdd(&g_syncM[bh], 1) == (LSEQ / MQT) - 1);
    __syncthreads();
    if (!s_last) return;
    __threadfence();                     // acquire other blocks' g_Mkey writes

    unsigned* skeys = (unsigned*)smf;    // reuse Ks region: 8 KB
    unsigned* hist  = (unsigned*)smf + LSEQ;
    for (int i = t; i < LSEQ; i += 1024)
        skeys[i] = g_Mkey[bh * LSEQ + i];
    if (t == 0) {
        s_prefix = 0u; s_remaining = USEL; s_cnt = 0; s_eq = 0;
        g_syncM[bh] = 0;                 // self-reset for next graph replay
    }
    __syncthreads();

    const unsigned himask[4] = {0u, 0xFF000000u, 0xFFFF0000u, 0xFFFFFF00u};
#pragma unroll
    for (int r = 0; r < 4; r++) {
        int shift = 24 - 8 * r;
        if (t < 256) hist[t] = 0;
        __syncthreads();
        unsigned pfx = s_prefix;
        for (int i = t; i < LSEQ; i += 1024) {
            unsigned k = skeys[i];
            if ((k & himask[r]) == pfx)
                atomicAdd(&hist[(k >> shift) & 255u], 1u);
        }
        __syncthreads();
        if (t < 32) {
            unsigned v[8], tot = 0;
#pragma unroll
            for (int c = 0; c < 8; c++) { v[c] = hist[t * 8 + c]; tot += v[c]; }
            unsigned suf = tot;
#pragma unroll
            for (int off = 1; off < 32; off <<= 1) {
                unsigned o = __shfl_down_sync(0xFFFFFFFFu, suf, off);
                if (t + off < 32) suf += o;
            }
            unsigned below = suf - tot;
            int rem = s_remaining;
#pragma unroll
            for (int c = 7; c >= 0; c--) {
                unsigned here = below + v[c];
                if ((int)here >= rem && (int)below < rem) {
                    s_prefix = pfx | ((unsigned)(t * 8 + c) << shift);
                    s_remaining = rem - (int)below;
                }
                below = here;
            }
        }
        __syncthreads();
    }

    unsigned T = s_prefix;
    int need_eq = s_remaining;

    for (int i = t; i < LSEQ; i += 1024) {
        unsigned k = skeys[i];
        if (k > T) {
            int p = atomicAdd(&s_cnt, 1);
            g_topk[bh * USEL + p] = i;
        } else if (k == T) {
            int p = atomicAdd(&s_eq, 1);
            if (p < 64) ebuf[p] = i;
        }
    }
    __syncthreads();

    int cnt_gt = s_cnt, cnt_eq = s_eq;
    if (cnt_eq == need_eq) {
        if (t < cnt_eq)
            g_topk[bh * USEL + cnt_gt + t] = ebuf[t];
    } else if (t == 0) {
        if (cnt_eq <= 64) {
            for (int n = 0; n < need_eq; n++) {
                int bi = -1, bv = LSEQ;
                for (int j2 = 0; j2 < cnt_eq; j2++)
                    if (ebuf[j2] < bv) { bv = ebuf[j2]; bi = j2; }
                g_topk[bh * USEL + cnt_gt + n] = bv;
                ebuf[bi] = LSEQ;
            }
        } else {
            int n = 0;
            for (int i = 0; i < LSEQ && n < need_eq; i++)
                if (skeys[i] == T) g_topk[bh * USEL + cnt_gt + n++] = i;
        }
    }
}

// ================= 5. attention partials: one 64-key tile per block (R8) =====
__global__ __launch_bounds__(256) void attn_kernel(const float* __restrict__ Q,
                                                   const float* __restrict__ K,
                                                   const float* __restrict__ V) {
    extern __shared__ float sm[];
    float* Qs = sm + A_QS;
    float* Ks = sm + A_KS;
    float* Vs = sm + A_VS;
    float* Pt = sm + A_PT;

    int ch = blockIdx.x, bh = blockIdx.y;
    int t = threadIdx.x;
    int i = t >> 5, j = t & 31;
    int kb = ch * CHK;

    const float* Kb = K + (size_t)bh * LSEQ * DIM;
    const float* Vb = V + (size_t)bh * LSEQ * DIM;

    for (int e = t; e < USEL * DIM; e += 256) {
        int q = e >> 6, d = e & 63;
        int qi = g_topk[bh * USEL + q];
        Qs[e] = Q[((size_t)bh * LSEQ + qi) * DIM + d] * 0.125f;
    }
#pragma unroll
    for (int rr = 0; rr < 4; rr++) {
        int f = t + rr * 256;
        int r = f >> 4, c4 = f & 15;
        *(float4*)&Ks[r * KVS + c4 * 4] =
            __ldg((const float4*)(Kb + (size_t)(kb + r) * DIM) + c4);
        *(float4*)&Vs[r * KVS + c4 * 4] =
            __ldg((const float4*)(Vb + (size_t)(kb + r) * DIM) + c4);
    }
    __syncthreads();

    float s0[5], s1[5];
#pragma unroll
    for (int a = 0; a < 5; a++) { s0[a] = 0.f; s1[a] = 0.f; }
#pragma unroll
    for (int d4 = 0; d4 < 16; d4++) {
        float4 k0 = *(const float4*)&Ks[j * KVS + d4 * 4];
        float4 k1 = *(const float4*)&Ks[(j + 32) * KVS + d4 * 4];
#pragma unroll
        for (int a = 0; a < 5; a++) {
            float4 qv = *(const float4*)&Qs[(i + 8 * a) * 64 + d4 * 4];
            float u0 = s0[a];
            u0 = fmaf(qv.x, k0.x, u0);
            u0 = fmaf(qv.y, k0.y, u0);
            u0 = fmaf(qv.z, k0.z, u0);
            u0 = fmaf(qv.w, k0.w, u0);
            s0[a] = u0;
            float u1 = s1[a];
            u1 = fmaf(qv.x, k1.x, u1);
            u1 = fmaf(qv.y, k1.y, u1);
            u1 = fmaf(qv.z, k1.z, u1);
            u1 = fmaf(qv.w, k1.w, u1);
            s1[a] = u1;
        }
    }

    float m_[5], l_[5], acc[5][2];
#pragma unroll
    for (int a = 0; a < 5; a++) {
        float tm = fmaxf(s0[a], s1[a]);
#pragma unroll
        for (int o = 16; o; o >>= 1)
            tm = fmaxf(tm, __shfl_xor_sync(0xFFFFFFFFu, tm, o));
        float p0 = __expf(s0[a] - tm);
        float p1 = __expf(s1[a] - tm);
        float su = p0 + p1;
#pragma unroll
        for (int o = 16; o; o >>= 1)
            su += __shfl_xor_sync(0xFFFFFFFFu, su, o);
        m_[a] = tm;
        l_[a] = su;
        acc[a][0] = 0.f;
        acc[a][1] = 0.f;
        Pt[(i * 5 + a) * 64 + j]      = p0;
        Pt[(i * 5 + a) * 64 + j + 32] = p1;
    }
    __syncwarp();

#pragma unroll
    for (int k4 = 0; k4 < 16; k4++) {
        int k = k4 * 4;
        float v00 = Vs[(k + 0) * KVS + j];
        float v01 = Vs[(k + 1) * KVS + j];
        float v02 = Vs[(k + 2) * KVS + j];
        float v03 = Vs[(k + 3) * KVS + j];
        float v10 = Vs[(k + 0) * KVS + j + 32];
        float v11 = Vs[(k + 1) * KVS + j + 32];
        float v12 = Vs[(k + 2) * KVS + j + 32];
        float v13 = Vs[(k + 3) * KVS + j + 32];
#pragma unroll
        for (int a = 0; a < 5; a++) {
            float4 p = *(const float4*)&Pt[(i * 5 + a) * 64 + k];
            float u0 = acc[a][0];
            u0 = fmaf(p.x, v00, u0);
            u0 = fmaf(p.y, v01, u0);
            u0 = fmaf(p.z, v02, u0);
            u0 = fmaf(p.w, v03, u0);
            acc[a][0] = u0;
            float u1 = acc[a][1];
            u1 = fmaf(p.x, v10, u1);
            u1 = fmaf(p.y, v11, u1);
            u1 = fmaf(p.z, v12, u1);
            u1 = fmaf(p.w, v13, u1);
            acc[a][1] = u1;
        }
    }

    float* pa = g_pacc + (size_t)(bh * NCH + ch) * USEL * DIM;
#pragma unroll
    for (int a = 0; a < 5; a++) {
        int q = i + 8 * a;
        pa[q * DIM + j]      = acc[a][0];
        pa[q * DIM + j + 32] = acc[a][1];
    }
    if (j == 0) {
#pragma unroll
        for (int a = 0; a < 5; a++) {
            g_pm[(bh * NCH + ch) * USEL + i + 8 * a] = m_[a];
            g_pl[(bh * NCH + ch) * USEL + i + 8 * a] = l_[a];
        }
    }
}

// ================= 6. merge partials, scatter into output (R8, 1280 blocks) ==
__global__ void merge_kernel(float* __restrict__ out) {
    int u = blockIdx.x, bh = blockIdx.y, d = threadIdx.x;
    float M = -1e30f;
#pragma unroll
    for (int c = 0; c < NCH; c++)
        M = fmaxf(M, g_pm[(bh * NCH + c) * USEL + u]);
    float L = 0.f, o = 0.f;
#pragma unroll
    for (int c = 0; c < NCH; c++) {
        float w = __expf(g_pm[(bh * NCH + c) * USEL + u] - M);
        L += g_pl[(bh * NCH + c) * USEL + u] * w;
        o = fmaf(g_pacc[((size_t)(bh * NCH + c) * USEL + u) * DIM + d], w, o);
    }
    int qi = g_topk[bh * USEL + u];
    out[((size_t)bh * LSEQ + qi) * DIM + d] = o / L;
}

// ================= launcher =================
extern "C" void kernel_launch(void* const* d_in, const int* in_sizes, int n_in,
                              void* d_out, int out_size) {
    const float* Q    = (const float*)d_in[0];
    const float* K    = (const float*)d_in[1];
    const float* V    = (const float*)d_in[2];
    const int*   idxs = (const int*)d_in[3];
    float* out = (float*)d_out;
    int u = in_sizes[3] / LSEQ;   // 40

    cudaFuncSetAttribute(m_kernel, cudaFuncAttributeMaxDynamicSharedMemorySize, M_SMEM);
    cudaFuncSetAttribute(attn_kernel, cudaFuncAttributeMaxDynamicSharedMemorySize, A_SMEM);

    mean_kernel<<<BH, 1024>>>(V);
    fill_kernel<<<(BH * LSEQ * 16) / 256, 256>>>((float4*)out);
    sort_kernel<<<LSEQ / 256, 256>>>(idxs, u);
    m_kernel<<<dim3(LSEQ / MQT, BH), 1024, M_SMEM>>>(Q, K);
    attn_kernel<<<dim3(NCH, BH), 256, A_SMEM>>>(Q, K, V);
    merge_kernel<<<dim3(USEL, BH), 64>>>(out);
}

// round 15
// speedup vs baseline: 1.2737x; 1.0396x over previous
#include <cuda_runtime.h>
#include <cuda_bf16.h>
#include <math.h>

// Problem constants (fixed bench shapes)
#define BH    32            // B*H = 4*8
#define LSEQ  2048          // sequence length
#define DIM   64            // head dim
#define USEL  40            // u = U_part
#define NCH   32            // key chunks for split-softmax attention
#define CHK   (LSEQ/NCH)    // 64 keys per chunk (single tile per block)
#define KVS   68            // padded smem row stride for attn K/V tiles
#define MCH   512           // m_kernel key-chunk size
#define MQT   512           // m_kernel q-tile (4 tiles x 32 bh = 128 blocks, 1 wave)

// m_kernel smem layout (bytes) — exact R8 layout
#define MS_K     0                                   // 512*64*4   = 131072
#define MS_IDX   (MCH * DIM * 4)                     // +512*40*2  =  40960
#define MS_OFF   (MS_IDX + MQT * USEL * 2)           // +512*4     =   2048
#define M_SMEM   (MS_OFF + MQT * 4)                  // 174080 B (170 KB)

#define A_QS    0
#define A_KS    (USEL * DIM)
#define A_VS    (A_KS + 64 * KVS)
#define A_PT    (A_VS + 64 * KVS)
#define A_SMEM  ((A_PT + 8 * 5 * 64) * 4)            // 55,296 B

// -------- scratch (device globals; no allocation allowed) --------
__device__ unsigned g_Mkey[BH * LSEQ];
__device__ int   g_topk[BH * USEL];
__device__ float g_meanV[BH * DIM];
__device__ float g_pm[BH * NCH * USEL];
__device__ float g_pl[BH * NCH * USEL];
__device__ float g_pacc[(size_t)BH * NCH * USEL * DIM];   // 10.5 MB
__device__ unsigned short g_sidx[LSEQ * USEL];      // chunk-sorted, PRE-MASKED local idx
__device__ unsigned g_soff[LSEQ];                   // packed chunk start offsets
__device__ int   g_syncM[BH];                       // m-block arrival counters (self-reset)

__device__ __forceinline__ unsigned f2key(float x) {
    unsigned k = __float_as_uint(x);
    return (k & 0x80000000u) ? ~k : (k | 0x80000000u);
}

// ================= 1. mean of V per (b,h): vectorized (R8) =================
__global__ __launch_bounds__(1024) void mean_kernel(const float* __restrict__ V) {
    __shared__ float4 sb[64][16];
    int bh = blockIdx.x, t = threadIdx.x;
    int part = t >> 4, c4 = t & 15;
    const float4* Vb = (const float4*)(V + (size_t)bh * LSEQ * DIM);
    float4 s = make_float4(0.f, 0.f, 0.f, 0.f);
    for (int l = part; l < LSEQ; l += 64) {
        float4 v = __ldg(Vb + l * 16 + c4);
        s.x += v.x; s.y += v.y; s.z += v.z; s.w += v.w;
    }
    sb[part][c4] = s;
    __syncthreads();
#pragma unroll
    for (int o = 32; o; o >>= 1) {
        if (part < o) {
            float4 a = sb[part][c4], b = sb[part + o][c4];
            a.x += b.x; a.y += b.y; a.z += b.z; a.w += b.w;
            sb[part][c4] = a;
        }
        __syncthreads();
    }
    if (t < 16) {
        float4 a = sb[0][t];
        a.x *= (1.0f / LSEQ); a.y *= (1.0f / LSEQ);
        a.z *= (1.0f / LSEQ); a.w *= (1.0f / LSEQ);
        ((float4*)g_meanV)[bh * 16 + t] = a;
    }
}

// ================= 2. broadcast-fill output with meanV (chip-wide, R8) =======
__global__ void fill_kernel(float4* __restrict__ out) {
    int i = blockIdx.x * blockDim.x + threadIdx.x;
    int bh = i >> 15;
    int d4 = i & 15;
    out[i] = ((const float4*)g_meanV)[bh * 16 + d4];
}

// ================= 2b. bucket samples by key-chunk; store LOCAL idx (R8) =====
__global__ void sort_kernel(const int* __restrict__ idxs, int u) {
    int q = blockIdx.x * blockDim.x + threadIdx.x;
    if (q >= LSEQ) return;
    const int* ip = idxs + (size_t)q * u;
    int cnt[4] = {0, 0, 0, 0};
#pragma unroll
    for (int s = 0; s < USEL; s++)
        cnt[__ldg(ip + s) >> 9]++;
    int st1 = cnt[0];
    int st2 = st1 + cnt[1];
    int st3 = st2 + cnt[2];
    g_soff[q] = (unsigned)st1 | ((unsigned)st2 << 8) | ((unsigned)st3 << 16);
    int pos[4] = {0, st1, st2, st3};
#pragma unroll
    for (int s = 0; s < USEL; s++) {
        int ki = __ldg(ip + s);
        int c = ki >> 9;
        g_sidx[q * USEL + pos[c]++] = (unsigned short)(ki & (MCH - 1));
    }
}

// ================= 3. M scores (R8) + fused per-bh top-40 radix tail (R13) ===
__global__ __launch_bounds__(1024, 1) void m_kernel(const float* __restrict__ Q,
                                                    const float* __restrict__ K) {
    extern __shared__ float smf[];
    float* Ks = smf;                                         // MCH x 64
    unsigned short* sIdx = (unsigned short*)((char*)smf + MS_IDX);
    unsigned* sOff = (unsigned*)((char*)smf + MS_OFF);

    __shared__ int s_last;
    __shared__ unsigned s_prefix;
    __shared__ int s_remaining, s_cnt, s_eq;
    __shared__ int ebuf[64];

    int t = threadIdx.x, lane = t & 31, warp = t >> 5;
    int g = lane >> 3, h = lane & 7;
    int bh = blockIdx.y;
    int qlo = blockIdx.x * MQT;

    // stage this q-tile's index lists (40 KB) and offsets (2 KB)
    {
        const uint4* src = (const uint4*)(g_sidx + (size_t)qlo * USEL);
        uint4* dst = (uint4*)sIdx;
        for (int f = t; f < (MQT * USEL * 2) / 16; f += 1024)
            dst[f] = __ldg(src + f);
        if (t < MQT) sOff[t] = g_soff[qlo + t];
    }

    const float* Kb = K + (size_t)bh * LSEQ * DIM;
    float mxs = -1e30f, sms = 0.f;

    for (int c = 0; c < LSEQ / MCH; c++) {
        int cb = c * MCH;
        __syncthreads();   // previous chunk fully consumed (also covers idx staging)
#pragma unroll
        for (int k = 0; k < (MCH * 16) / 1024; k++) {
            int f = t + k * 1024;
            ((float4*)Ks)[f] = __ldg((const float4*)(Kb + (size_t)cb * DIM) + f);
        }
        __syncthreads();

        for (int i = 0; i < MQT / 32; i++) {          // 16 queries per warp
            int ql = warp * (MQT / 32) + i;
            int q = qlo + ql;
            unsigned sw = sOff[ql];
            int lo = c ? (int)((sw >> (8 * (c - 1))) & 255u) : 0;
            int hi = (c < 3) ? (int)((sw >> (8 * c)) & 255u) : USEL;

            const unsigned short* sq = sIdx + ql * USEL;
            const float4* Q4 = (const float4*)(Q + ((size_t)bh * LSEQ + q) * DIM);
            float4 qa = __ldg(Q4 + h);
            float4 qb = __ldg(Q4 + h + 8);

            float mxq = -1e30f, smq = 0.f;
#pragma unroll 2
            for (int p0 = lo; p0 < hi; p0 += 4) {
                int p = p0 + g;
                bool act = p < hi;
                int kil = sq[min(p, hi - 1)];    // broadcast LDS.U16
                const float4* Kr = (const float4*)(Ks + (kil << 6));
                float4 a0 = Kr[h], a1 = Kr[h + 8];
                float e0 = qa.x * a0.x;          // two independent chains
                float e1 = qb.x * a1.x;
                e0 = fmaf(qa.y, a0.y, e0);
                e1 = fmaf(qb.y, a1.y, e1);
                e0 = fmaf(qa.z, a0.z, e0);
                e1 = fmaf(qb.z, a1.z, e1);
                e0 = fmaf(qa.w, a0.w, e0);
                e1 = fmaf(qb.w, a1.w, e1);
                float d = e0 + e1;
                d += __shfl_xor_sync(0xFFFFFFFFu, d, 1);
                d += __shfl_xor_sync(0xFFFFFFFFu, d, 2);
                d += __shfl_xor_sync(0xFFFFFFFFu, d, 4);
                if (act) { mxq = fmaxf(mxq, d); smq += d; }
            }
            mxq = fmaxf(mxq, __shfl_xor_sync(0xFFFFFFFFu, mxq, 8));
            mxq = fmaxf(mxq, __shfl_xor_sync(0xFFFFFFFFu, mxq, 16));
            smq += __shfl_xor_sync(0xFFFFFFFFu, smq, 8);
            smq += __shfl_xor_sync(0xFFFFFFFFu, smq, 16);
            if (lane == i) { mxs = fmaxf(mxs, mxq); sms += smq; }
        }
    }

    if (lane < MQT / 32) {
        int q = qlo + warp * (MQT / 32) + lane;
        g_Mkey[bh * LSEQ + q] = f2key(mxs - sms * (1.0f / LSEQ));
    }

    // ---------- tail: last q-tile block for this bh runs the radix select ----
    __threadfence();                     // publish g_Mkey writes
    __syncthreads();
    if (t == 0)
        s_last = (atomicAdd(&g_syncM[bh], 1) == (LSEQ / MQT) - 1);
    __syncthreads();
    if (!s_last) return;
    __threadfence();                     // acquire other blocks' g_Mkey writes

    unsigned* skeys = (unsigned*)smf;    // reuse Ks region: 8 KB
    unsigned* hist  = (unsigned*)smf + LSEQ;
    for (int i = t; i < LSEQ; i += 1024)
        skeys[i] = g_Mkey[bh * LSEQ + i];
    if (t == 0) {
        s_prefix = 0u; s_remaining = USEL; s_cnt = 0; s_eq = 0;
        g_syncM[bh] = 0;                 // self-reset for next graph replay
    }
    __syncthreads();

    const unsigned himask[4] = {0u, 0xFF000000u, 0xFFFF0000u, 0xFFFFFF00u};
#pragma unroll
    for (int r = 0; r < 4; r++) {
        int shift = 24 - 8 * r;
        if (t < 256) hist[t] = 0;
        __syncthreads();
        unsigned pfx = s_prefix;
        for (int i = t; i < LSEQ; i += 1024) {
            unsigned k = skeys[i];
            if ((k & himask[r]) == pfx)
                atomicAdd(&hist[(k >> shift) & 255u], 1u);
        }
        __syncthreads();
        if (t < 32) {
            unsigned v[8], tot = 0;
#pragma unroll
            for (int c = 0; c < 8; c++) { v[c] = hist[t * 8 + c]; tot += v[c]; }
            unsigned suf = tot;
#pragma unroll
            for (int off = 1; off < 32; off <<= 1) {
                unsigned o = __shfl_down_sync(0xFFFFFFFFu, suf, off);
                if (t + off < 32) suf += o;
            }
            unsigned below = suf - tot;
            int rem = s_remaining;
#pragma unroll
            for (int c = 7; c >= 0; c--) {
                unsigned here = below + v[c];
                if ((int)here >= rem && (int)below < rem) {
                    s_prefix = pfx | ((unsigned)(t * 8 + c) << shift);
                    s_remaining = rem - (int)below;
                }
                below = here;
            }
        }
        __syncthreads();
    }

    unsigned T = s_prefix;
    int need_eq = s_remaining;

    for (int i = t; i < LSEQ; i += 1024) {
        unsigned k = skeys[i];
        if (k > T) {
            int p = atomicAdd(&s_cnt, 1);
            g_topk[bh * USEL + p] = i;
        } else if (k == T) {
            int p = atomicAdd(&s_eq, 1);
            if (p < 64) ebuf[p] = i;
        }
    }
    __syncthreads();

    int cnt_gt = s_cnt, cnt_eq = s_eq;
    if (cnt_eq == need_eq) {
        if (t < cnt_eq)
            g_topk[bh * USEL + cnt_gt + t] = ebuf[t];
    } else if (t == 0) {
        if (cnt_eq <= 64) {
            for (int n = 0; n < need_eq; n++) {
                int bi = -1, bv = LSEQ;
                for (int j2 = 0; j2 < cnt_eq; j2++)
                    if (ebuf[j2] < bv) { bv = ebuf[j2]; bi = j2; }
                g_topk[bh * USEL + cnt_gt + n] = bv;
                ebuf[bi] = LSEQ;
            }
        } else {
            int n = 0;
            for (int i = 0; i < LSEQ && n < need_eq; i++)
                if (skeys[i] == T) g_topk[bh * USEL + cnt_gt + n++] = i;
        }
    }
}

// ================= 5. attention partials: one 64-key tile per block (R8) =====
__global__ __launch_bounds__(256) void attn_kernel(const float* __restrict__ Q,
                                                   const float* __restrict__ K,
                                                   const float* __restrict__ V) {
    extern __shared__ float sm[];
    float* Qs = sm + A_QS;
    float* Ks = sm + A_KS;
    float* Vs = sm + A_VS;
    float* Pt = sm + A_PT;

    int ch = blockIdx.x, bh = blockIdx.y;
    int t = threadIdx.x;
    int i = t >> 5, j = t & 31;
    int kb = ch * CHK;

    const float* Kb = K + (size_t)bh * LSEQ * DIM;
    const float* Vb = V + (size_t)bh * LSEQ * DIM;

    for (int e = t; e < USEL * DIM; e += 256) {
        int q = e >> 6, d = e & 63;
        int qi = g_topk[bh * USEL + q];
        Qs[e] = Q[((size_t)bh * LSEQ + qi) * DIM + d] * 0.125f;
    }
#pragma unroll
    for (int rr = 0; rr < 4; rr++) {
        int f = t + rr * 256;
        int r = f >> 4, c4 = f & 15;
        *(float4*)&Ks[r * KVS + c4 * 4] =
            __ldg((const float4*)(Kb + (size_t)(kb + r) * DIM) + c4);
        *(float4*)&Vs[r * KVS + c4 * 4] =
            __ldg((const float4*)(Vb + (size_t)(kb + r) * DIM) + c4);
    }
    __syncthreads();

    float s0[5], s1[5];
#pragma unroll
    for (int a = 0; a < 5; a++) { s0[a] = 0.f; s1[a] = 0.f; }
#pragma unroll
    for (int d4 = 0; d4 < 16; d4++) {
        float4 k0 = *(const float4*)&Ks[j * KVS + d4 * 4];
        float4 k1 = *(const float4*)&Ks[(j + 32) * KVS + d4 * 4];
#pragma unroll
        for (int a = 0; a < 5; a++) {
            float4 qv = *(const float4*)&Qs[(i + 8 * a) * 64 + d4 * 4];
            float u0 = s0[a];
            u0 = fmaf(qv.x, k0.x, u0);
            u0 = fmaf(qv.y, k0.y, u0);
            u0 = fmaf(qv.z, k0.z, u0);
            u0 = fmaf(qv.w, k0.w, u0);
            s0[a] = u0;
            float u1 = s1[a];
            u1 = fmaf(qv.x, k1.x, u1);
            u1 = fmaf(qv.y, k1.y, u1);
            u1 = fmaf(qv.z, k1.z, u1);
            u1 = fmaf(qv.w, k1.w, u1);
            s1[a] = u1;
        }
    }

    float m_[5], l_[5], acc[5][2];
#pragma unroll
    for (int a = 0; a < 5; a++) {
        float tm = fmaxf(s0[a], s1[a]);
#pragma unroll
        for (int o = 16; o; o >>= 1)
            tm = fmaxf(tm, __shfl_xor_sync(0xFFFFFFFFu, tm, o));
        float p0 = __expf(s0[a] - tm);
        float p1 = __expf(s1[a] - tm);
        float su = p0 + p1;
#pragma unroll
        for (int o = 16; o; o >>= 1)
            su += __shfl_xor_sync(0xFFFFFFFFu, su, o);
        m_[a] = tm;
        l_[a] = su;
        acc[a][0] = 0.f;
        acc[a][1] = 0.f;
        Pt[(i * 5 + a) * 64 + j]      = p0;
        Pt[(i * 5 + a) * 64 + j + 32] = p1;
    }
    __syncwarp();

#pragma unroll
    for (int k4 = 0; k4 < 16; k4++) {
        int k = k4 * 4;
        float v00 = Vs[(k + 0) * KVS + j];
        float v01 = Vs[(k + 1) * KVS + j];
        float v02 = Vs[(k + 2) * KVS + j];
        float v03 = Vs[(k + 3) * KVS + j];
        float v10 = Vs[(k + 0) * KVS + j + 32];
        float v11 = Vs[(k + 1) * KVS + j + 32];
        float v12 = Vs[(k + 2) * KVS + j + 32];
        float v13 = Vs[(k + 3) * KVS + j + 32];
#pragma unroll
        for (int a = 0; a < 5; a++) {
            float4 p = *(const float4*)&Pt[(i * 5 + a) * 64 + k];
            float u0 = acc[a][0];
            u0 = fmaf(p.x, v00, u0);
            u0 = fmaf(p.y, v01, u0);
            u0 = fmaf(p.z, v02, u0);
            u0 = fmaf(p.w, v03, u0);
            acc[a][0] = u0;
            float u1 = acc[a][1];
            u1 = fmaf(p.x, v10, u1);
            u1 = fmaf(p.y, v11, u1);
            u1 = fmaf(p.z, v12, u1);
            u1 = fmaf(p.w, v13, u1);
            acc[a][1] = u1;
        }
    }

    float* pa = g_pacc + (size_t)(bh * NCH + ch) * USEL * DIM;
#pragma unroll
    for (int a = 0; a < 5; a++) {
        int q = i + 8 * a;
        pa[q * DIM + j]      = acc[a][0];
        pa[q * DIM + j + 32] = acc[a][1];
    }
    if (j == 0) {
#pragma unroll
        for (int a = 0; a < 5; a++) {
            g_pm[(bh * NCH + ch) * USEL + i + 8 * a] = m_[a];
            g_pl[(bh * NCH + ch) * USEL + i + 8 * a] = l_[a];
        }
    }
}

// ================= 6. merge partials, scatter into output (R8, 1280 blocks) ==
__global__ void merge_kernel(float* __restrict__ out) {
    int u = blockIdx.x, bh = blockIdx.y, d = threadIdx.x;
    float M = -1e30f;
#pragma unroll
    for (int c = 0; c < NCH; c++)
        M = fmaxf(M, g_pm[(bh * NCH + c) * USEL + u]);
    float L = 0.f, o = 0.f;
#pragma unroll
    for (int c = 0; c < NCH; c++) {
        float w = __expf(g_pm[(bh * NCH + c) * USEL + u] - M);
        L += g_pl[(bh * NCH + c) * USEL + u] * w;
        o = fmaf(g_pacc[((size_t)(bh * NCH + c) * USEL + u) * DIM + d], w, o);
    }
    int qi = g_topk[bh * USEL + u];
    out[((size_t)bh * LSEQ + qi) * DIM + d] = o / L;
}

// ================= launcher: fork mean+fill onto a side branch ================
extern "C" void kernel_launch(void* const* d_in, const int* in_sizes, int n_in,
                              void* d_out, int out_size) {
    const float* Q    = (const float*)d_in[0];
    const float* K    = (const float*)d_in[1];
    const float* V    = (const float*)d_in[2];
    const int*   idxs = (const int*)d_in[3];
    float* out = (float*)d_out;
    int u = in_sizes[3] / LSEQ;   // 40

    // one-time host-side objects (no device memory involved)
    static cudaStream_t s2 = nullptr;
    static cudaEvent_t evFork = nullptr, evJoin = nullptr;
    if (s2 == nullptr) {
        cudaStreamCreateWithFlags(&s2, cudaStreamNonBlocking);
        cudaEventCreateWithFlags(&evFork, cudaEventDisableTiming);
        cudaEventCreateWithFlags(&evJoin, cudaEventDisableTiming);
        cudaFuncSetAttribute(m_kernel, cudaFuncAttributeMaxDynamicSharedMemorySize, M_SMEM);
        cudaFuncSetAttribute(attn_kernel, cudaFuncAttributeMaxDynamicSharedMemorySize, A_SMEM);
    }

    // fork: side branch does mean -> fill (only merge depends on it)
    cudaEventRecord(evFork, 0);
    cudaStreamWaitEvent(s2, evFork, 0);
    mean_kernel<<<BH, 1024, 0, s2>>>(V);
    fill_kernel<<<(BH * LSEQ * 16) / 256, 256, 0, s2>>>((float4*)out);
    cudaEventRecord(evJoin, s2);

    // critical path: sort -> m(+topk tail) -> attn
    sort_kernel<<<LSEQ / 256, 256>>>(idxs, u);
    m_kernel<<<dim3(LSEQ / MQT, BH), 1024, M_SMEM>>>(Q, K);
    attn_kernel<<<dim3(NCH, BH), 256, A_SMEM>>>(Q, K, V);

    // join: merge needs fill (output background) + attn partials
    cudaStreamWaitEvent(0, evJoin, 0);
    merge_kernel<<<dim3(USEL, BH), 64>>>(out);
}

// round 16
// speedup vs baseline: 1.2797x; 1.0047x over previous
#include <cuda_runtime.h>
#include <cuda_bf16.h>
#include <math.h>

// Problem constants (fixed bench shapes)
#define BH    32            // B*H = 4*8
#define LSEQ  2048          // sequence length
#define DIM   64            // head dim
#define USEL  40            // u = U_part
#define NCH   32            // key chunks for split-softmax attention
#define CHK   (LSEQ/NCH)    // 64 keys per chunk (single tile per block)
#define KVS   68            // padded smem row stride for attn K/V tiles
#define MCH   512           // m_kernel key-chunk size
#define MQT   512           // m_kernel q-tile (4 tiles x 32 bh = 128 blocks, 1 wave)

// m_kernel smem layout (bytes)
#define MS_K     0                                   // 512*64*4   = 131072
#define MS_IDX   (MCH * DIM * 4)                     // +512*40*2  =  40960
#define MS_OFF   (MS_IDX + MQT * USEL * 2)           // +512*4     =   2048
#define M_SMEM   (MS_OFF + MQT * 4)                  // 174080 B (170 KB)

// attn smem layout (floats) — Qs removed: 44 KB -> 5 blocks/SM
#define A_KS    0
#define A_VS    (64 * KVS)
#define A_PT    (2 * 64 * KVS)
#define A_SMEM  ((A_PT + 8 * 5 * 64) * 4)            // 45,056 B

// -------- scratch (device globals; no allocation allowed) --------
__device__ unsigned g_Mkey[BH * LSEQ];
__device__ int   g_topk[BH * USEL];
__device__ float g_meanV[BH * DIM];
__device__ float g_pm[BH * NCH * USEL];
__device__ float g_pl[BH * NCH * USEL];
__device__ float g_pacc[(size_t)BH * NCH * USEL * DIM];   // 10.5 MB
__device__ int   g_syncM[BH];                       // m-block arrival counters (self-reset)

__device__ __forceinline__ unsigned f2key(float x) {
    unsigned k = __float_as_uint(x);
    return (k & 0x80000000u) ? ~k : (k | 0x80000000u);
}

// ================= 1. mean of V per (b,h): vectorized (R8) =================
__global__ __launch_bounds__(1024) void mean_kernel(const float* __restrict__ V) {
    __shared__ float4 sb[64][16];
    int bh = blockIdx.x, t = threadIdx.x;
    int part = t >> 4, c4 = t & 15;
    const float4* Vb = (const float4*)(V + (size_t)bh * LSEQ * DIM);
    float4 s = make_float4(0.f, 0.f, 0.f, 0.f);
    for (int l = part; l < LSEQ; l += 64) {
        float4 v = __ldg(Vb + l * 16 + c4);
        s.x += v.x; s.y += v.y; s.z += v.z; s.w += v.w;
    }
    sb[part][c4] = s;
    __syncthreads();
#pragma unroll
    for (int o = 32; o; o >>= 1) {
        if (part < o) {
            float4 a = sb[part][c4], b = sb[part + o][c4];
            a.x += b.x; a.y += b.y; a.z += b.z; a.w += b.w;
            sb[part][c4] = a;
        }
        __syncthreads();
    }
    if (t < 16) {
        float4 a = sb[0][t];
        a.x *= (1.0f / LSEQ); a.y *= (1.0f / LSEQ);
        a.z *= (1.0f / LSEQ); a.w *= (1.0f / LSEQ);
        ((float4*)g_meanV)[bh * 16 + t] = a;
    }
}

// ================= 2. broadcast-fill output with meanV (chip-wide) =======
__global__ void fill_kernel(float4* __restrict__ out) {
    int i = blockIdx.x * blockDim.x + threadIdx.x;
    int bh = i >> 15;
    int d4 = i & 15;
    out[i] = ((const float4*)g_meanV)[bh * 16 + d4];
}

// ================= 3. M scores + fused idx-sort head + top-40 radix tail =====
// Staging head: threads t<512 counting-sort their query's 40 sample indices
// directly into smem (replaces sort_kernel + the 40KB/block g_sidx reload).
__global__ __launch_bounds__(1024, 1) void m_kernel(const float* __restrict__ Q,
                                                    const float* __restrict__ K,
                                                    const int* __restrict__ idxs,
                                                    int u) {
    extern __shared__ float smf[];
    float* Ks = smf;                                         // MCH x 64
    unsigned short* sIdx = (unsigned short*)((char*)smf + MS_IDX);
    unsigned* sOff = (unsigned*)((char*)smf + MS_OFF);

    __shared__ int s_last;
    __shared__ unsigned s_prefix;
    __shared__ int s_remaining, s_cnt, s_eq;
    __shared__ int ebuf[64];

    int t = threadIdx.x, lane = t & 31, warp = t >> 5;
    int g = lane >> 3, h = lane & 7;
    int bh = blockIdx.y;
    int qlo = blockIdx.x * MQT;

    // head: per-thread counting sort of this q-tile's sample indices into smem
    if (t < MQT) {
        const int* ip = idxs + (size_t)(qlo + t) * u;
        int cnt[4] = {0, 0, 0, 0};
#pragma unroll
        for (int s = 0; s < USEL; s++)
            cnt[__ldg(ip + s) >> 9]++;
        int st1 = cnt[0];
        int st2 = st1 + cnt[1];
        int st3 = st2 + cnt[2];
        sOff[t] = (unsigned)st1 | ((unsigned)st2 << 8) | ((unsigned)st3 << 16);
        int pos[4] = {0, st1, st2, st3};
        unsigned short* sq = sIdx + t * USEL;
#pragma unroll
        for (int s = 0; s < USEL; s++) {
            int ki = __ldg(ip + s);
            int c = ki >> 9;
            sq[pos[c]++] = (unsigned short)(ki & (MCH - 1));
        }
    }

    const float* Kb = K + (size_t)bh * LSEQ * DIM;
    float mxs = -1e30f, sms = 0.f;

    for (int c = 0; c < LSEQ / MCH; c++) {
        int cb = c * MCH;
        __syncthreads();   // previous chunk consumed (also covers idx-sort head)
#pragma unroll
        for (int k = 0; k < (MCH * 16) / 1024; k++) {
            int f = t + k * 1024;
            ((float4*)Ks)[f] = __ldg((const float4*)(Kb + (size_t)cb * DIM) + f);
        }
        __syncthreads();

        for (int i = 0; i < MQT / 32; i++) {          // 16 queries per warp
            int ql = warp * (MQT / 32) + i;
            int q = qlo + ql;
            unsigned sw = sOff[ql];
            int lo = c ? (int)((sw >> (8 * (c - 1))) & 255u) : 0;
            int hi = (c < 3) ? (int)((sw >> (8 * c)) & 255u) : USEL;

            const unsigned short* sq = sIdx + ql * USEL;
            const float4* Q4 = (const float4*)(Q + ((size_t)bh * LSEQ + q) * DIM);
            float4 qa = __ldg(Q4 + h);
            float4 qb = __ldg(Q4 + h + 8);

            float mxq = -1e30f, smq = 0.f;
#pragma unroll 2
            for (int p0 = lo; p0 < hi; p0 += 4) {
                int p = p0 + g;
                bool act = p < hi;
                int kil = sq[min(p, hi - 1)];    // broadcast LDS.U16
                const float4* Kr = (const float4*)(Ks + (kil << 6));
                float4 a0 = Kr[h], a1 = Kr[h + 8];
                float e0 = qa.x * a0.x;          // two independent chains
                float e1 = qb.x * a1.x;
                e0 = fmaf(qa.y, a0.y, e0);
                e1 = fmaf(qb.y, a1.y, e1);
                e0 = fmaf(qa.z, a0.z, e0);
                e1 = fmaf(qb.z, a1.z, e1);
                e0 = fmaf(qa.w, a0.w, e0);
                e1 = fmaf(qb.w, a1.w, e1);
                float d = e0 + e1;
                d += __shfl_xor_sync(0xFFFFFFFFu, d, 1);
                d += __shfl_xor_sync(0xFFFFFFFFu, d, 2);
                d += __shfl_xor_sync(0xFFFFFFFFu, d, 4);
                if (act) { mxq = fmaxf(mxq, d); smq += d; }
            }
            mxq = fmaxf(mxq, __shfl_xor_sync(0xFFFFFFFFu, mxq, 8));
            mxq = fmaxf(mxq, __shfl_xor_sync(0xFFFFFFFFu, mxq, 16));
            smq += __shfl_xor_sync(0xFFFFFFFFu, smq, 8);
            smq += __shfl_xor_sync(0xFFFFFFFFu, smq, 16);
            if (lane == i) { mxs = fmaxf(mxs, mxq); sms += smq; }
        }
    }

    if (lane < MQT / 32) {
        int q = qlo + warp * (MQT / 32) + lane;
        g_Mkey[bh * LSEQ + q] = f2key(mxs - sms * (1.0f / LSEQ));
    }

    // ---------- tail: last q-tile block for this bh runs the radix select ----
    __threadfence();                     // publish g_Mkey writes
    __syncthreads();
    if (t == 0)
        s_last = (atomicAdd(&g_syncM[bh], 1) == (LSEQ / MQT) - 1);
    __syncthreads();
    if (!s_last) return;
    __threadfence();                     // acquire other blocks' g_Mkey writes

    unsigned* skeys = (unsigned*)smf;    // reuse Ks region: 8 KB
    unsigned* hist  = (unsigned*)smf + LSEQ;
    for (int i = t; i < LSEQ; i += 1024)
        skeys[i] = g_Mkey[bh * LSEQ + i];
    if (t == 0) {
        s_prefix = 0u; s_remaining = USEL; s_cnt = 0; s_eq = 0;
        g_syncM[bh] = 0;                 // self-reset for next graph replay
    }
    __syncthreads();

    const unsigned himask[4] = {0u, 0xFF000000u, 0xFFFF0000u, 0xFFFFFF00u};
#pragma unroll
    for (int r = 0; r < 4; r++) {
        int shift = 24 - 8 * r;
        if (t < 256) hist[t] = 0;
        __syncthreads();
        unsigned pfx = s_prefix;
        for (int i = t; i < LSEQ; i += 1024) {
            unsigned k = skeys[i];
            if ((k & himask[r]) == pfx)
                atomicAdd(&hist[(k >> shift) & 255u], 1u);
        }
        __syncthreads();
        if (t < 32) {
            unsigned v[8], tot = 0;
#pragma unroll
            for (int c = 0; c < 8; c++) { v[c] = hist[t * 8 + c]; tot += v[c]; }
            unsigned suf = tot;
#pragma unroll
            for (int off = 1; off < 32; off <<= 1) {
                unsigned o = __shfl_down_sync(0xFFFFFFFFu, suf, off);
                if (t + off < 32) suf += o;
            }
            unsigned below = suf - tot;
            int rem = s_remaining;
#pragma unroll
            for (int c = 7; c >= 0; c--) {
                unsigned here = below + v[c];
                if ((int)here >= rem && (int)below < rem) {
                    s_prefix = pfx | ((unsigned)(t * 8 + c) << shift);
                    s_remaining = rem - (int)below;
                }
                below = here;
            }
        }
        __syncthreads();
    }

    unsigned T = s_prefix;
    int need_eq = s_remaining;

    for (int i = t; i < LSEQ; i += 1024) {
        unsigned k = skeys[i];
        if (k > T) {
            int p = atomicAdd(&s_cnt, 1);
            g_topk[bh * USEL + p] = i;
        } else if (k == T) {
            int p = atomicAdd(&s_eq, 1);
            if (p < 64) ebuf[p] = i;
        }
    }
    __syncthreads();

    int cnt_gt = s_cnt, cnt_eq = s_eq;
    if (cnt_eq == need_eq) {
        if (t < cnt_eq)
            g_topk[bh * USEL + cnt_gt + t] = ebuf[t];
    } else if (t == 0) {
        if (cnt_eq <= 64) {
            for (int n = 0; n < need_eq; n++) {
                int bi = -1, bv = LSEQ;
                for (int j2 = 0; j2 < cnt_eq; j2++)
                    if (ebuf[j2] < bv) { bv = ebuf[j2]; bi = j2; }
                g_topk[bh * USEL + cnt_gt + n] = bv;
                ebuf[bi] = LSEQ;
            }
        } else {
            int n = 0;
            for (int i = 0; i < LSEQ && n < need_eq; i++)
                if (skeys[i] == T) g_topk[bh * USEL + cnt_gt + n++] = i;
        }
    }
}

// ================= 5. attention partials: Q via broadcast LDG (no Qs tile) ===
// smem = K/V tiles + warp-private Pt only (44 KB -> 5 blocks/SM).
// Scores scaled by 1/8 once, after accumulation.
__global__ __launch_bounds__(256) void attn_kernel(const float* __restrict__ Q,
                                                   const float* __restrict__ K,
                                                   const float* __restrict__ V) {
    extern __shared__ float sm[];
    float* Ks = sm + A_KS;
    float* Vs = sm + A_VS;
    float* Pt = sm + A_PT;

    int ch = blockIdx.x, bh = blockIdx.y;
    int t = threadIdx.x;
    int i = t >> 5, j = t & 31;
    int kb = ch * CHK;

    const float* Kb = K + (size_t)bh * LSEQ * DIM;
    const float* Vb = V + (size_t)bh * LSEQ * DIM;

    // per-warp query row pointers (warp-uniform broadcast reads)
    const float4* Qp[5];
#pragma unroll
    for (int a = 0; a < 5; a++) {
        int qi = g_topk[bh * USEL + i + 8 * a];
        Qp[a] = (const float4*)(Q + ((size_t)bh * LSEQ + qi) * DIM);
    }

#pragma unroll
    for (int rr = 0; rr < 4; rr++) {
        int f = t + rr * 256;
        int r = f >> 4, c4 = f & 15;
        *(float4*)&Ks[r * KVS + c4 * 4] =
            __ldg((const float4*)(Kb + (size_t)(kb + r) * DIM) + c4);
        *(float4*)&Vs[r * KVS + c4 * 4] =
            __ldg((const float4*)(Vb + (size_t)(kb + r) * DIM) + c4);
    }
    __syncthreads();

    float s0[5], s1[5];
#pragma unroll
    for (int a = 0; a < 5; a++) { s0[a] = 0.f; s1[a] = 0.f; }
#pragma unroll
    for (int d4 = 0; d4 < 16; d4++) {
        float4 k0 = *(const float4*)&Ks[j * KVS + d4 * 4];
        float4 k1 = *(const float4*)&Ks[(j + 32) * KVS + d4 * 4];
#pragma unroll
        for (int a = 0; a < 5; a++) {
            float4 qv = __ldg(Qp[a] + d4);   // warp-uniform broadcast, L1-hot
            float u0 = s0[a];
            u0 = fmaf(qv.x, k0.x, u0);
            u0 = fmaf(qv.y, k0.y, u0);
            u0 = fmaf(qv.z, k0.z, u0);
            u0 = fmaf(qv.w, k0.w, u0);
            s0[a] = u0;
            float u1 = s1[a];
            u1 = fmaf(qv.x, k1.x, u1);
            u1 = fmaf(qv.y, k1.y, u1);
            u1 = fmaf(qv.z, k1.z, u1);
            u1 = fmaf(qv.w, k1.w, u1);
            s1[a] = u1;
        }
    }

    float m_[5], l_[5], acc[5][2];
#pragma unroll
    for (int a = 0; a < 5; a++) {
        float v0 = s0[a] * 0.125f;           // apply 1/sqrt(D) once
        float v1 = s1[a] * 0.125f;
        float tm = fmaxf(v0, v1);
#pragma unroll
        for (int o = 16; o; o >>= 1)
            tm = fmaxf(tm, __shfl_xor_sync(0xFFFFFFFFu, tm, o));
        float p0 = __expf(v0 - tm);
        float p1 = __expf(v1 - tm);
        float su = p0 + p1;
#pragma unroll
        for (int o = 16; o; o >>= 1)
            su += __shfl_xor_sync(0xFFFFFFFFu, su, o);
        m_[a] = tm;
        l_[a] = su;
        acc[a][0] = 0.f;
        acc[a][1] = 0.f;
        Pt[(i * 5 + a) * 64 + j]      = p0;
        Pt[(i * 5 + a) * 64 + j + 32] = p1;
    }
    __syncwarp();

#pragma unroll
    for (int k4 = 0; k4 < 16; k4++) {
        int k = k4 * 4;
        float v00 = Vs[(k + 0) * KVS + j];
        float v01 = Vs[(k + 1) * KVS + j];
        float v02 = Vs[(k + 2) * KVS + j];
        float v03 = Vs[(k + 3) * KVS + j];
        float v10 = Vs[(k + 0) * KVS + j + 32];
        float v11 = Vs[(k + 1) * KVS + j + 32];
        float v12 = Vs[(k + 2) * KVS + j + 32];
        float v13 = Vs[(k + 3) * KVS + j + 32];
#pragma unroll
        for (int a = 0; a < 5; a++) {
            float4 p = *(const float4*)&Pt[(i * 5 + a) * 64 + k];
            float u0 = acc[a][0];
            u0 = fmaf(p.x, v00, u0);
            u0 = fmaf(p.y, v01, u0);
            u0 = fmaf(p.z, v02, u0);
            u0 = fmaf(p.w, v03, u0);
            acc[a][0] = u0;
            float u1 = acc[a][1];
            u1 = fmaf(p.x, v10, u1);
            u1 = fmaf(p.y, v11, u1);
            u1 = fmaf(p.z, v12, u1);
            u1 = fmaf(p.w, v13, u1);
            acc[a][1] = u1;
        }
    }

    float* pa = g_pacc + (size_t)(bh * NCH + ch) * USEL * DIM;
#pragma unroll
    for (int a = 0; a < 5; a++) {
        int q = i + 8 * a;
        pa[q * DIM + j]      = acc[a][0];
        pa[q * DIM + j + 32] = acc[a][1];
    }
    if (j == 0) {
#pragma unroll
        for (int a = 0; a < 5; a++) {
            g_pm[(bh * NCH + ch) * USEL + i + 8 * a] = m_[a];
            g_pl[(bh * NCH + ch) * USEL + i + 8 * a] = l_[a];
        }
    }
}

// ================= 6. merge partials, scatter into output (1280 blocks) ==
__global__ void merge_kernel(float* __restrict__ out) {
    int u = blockIdx.x, bh = blockIdx.y, d = threadIdx.x;
    float M = -1e30f;
#pragma unroll
    for (int c = 0; c < NCH; c++)
        M = fmaxf(M, g_pm[(bh * NCH + c) * USEL + u]);
    float L = 0.f, o = 0.f;
#pragma unroll
    for (int c = 0; c < NCH; c++) {
        float w = __expf(g_pm[(bh * NCH + c) * USEL + u] - M);
        L += g_pl[(bh * NCH + c) * USEL + u] * w;
        o = fmaf(g_pacc[((size_t)(bh * NCH + c) * USEL + u) * DIM + d], w, o);
    }
    int qi = g_topk[bh * USEL + u];
    out[((size_t)bh * LSEQ + qi) * DIM + d] = o / L;
}

// ================= launcher: fork mean+fill onto a side branch ================
extern "C" void kernel_launch(void* const* d_in, const int* in_sizes, int n_in,
                              void* d_out, int out_size) {
    const float* Q    = (const float*)d_in[0];
    const float* K    = (const float*)d_in[1];
    const float* V    = (const float*)d_in[2];
    const int*   idxs = (const int*)d_in[3];
    float* out = (float*)d_out;
    int u = in_sizes[3] / LSEQ;   // 40

    // one-time host-side objects (no device memory involved)
    static cudaStream_t s2 = nullptr;
    static cudaEvent_t evFork = nullptr, evJoin = nullptr;
    if (s2 == nullptr) {
        cudaStreamCreateWithFlags(&s2, cudaStreamNonBlocking);
        cudaEventCreateWithFlags(&evFork, cudaEventDisableTiming);
        cudaEventCreateWithFlags(&evJoin, cudaEventDisableTiming);
        cudaFuncSetAttribute(m_kernel, cudaFuncAttributeMaxDynamicSharedMemorySize, M_SMEM);
        cudaFuncSetAttribute(attn_kernel, cudaFuncAttributeMaxDynamicSharedMemorySize, A_SMEM);
    }

    // fork: side branch does mean -> fill (only merge depends on it)
    cudaEventRecord(evFork, 0);
    cudaStreamWaitEvent(s2, evFork, 0);
    mean_kernel<<<BH, 1024, 0, s2>>>(V);
    fill_kernel<<<(BH * LSEQ * 16) / 256, 256, 0, s2>>>((float4*)out);
    cudaEventRecord(evJoin, s2);

    // critical path: m(+idx-sort head, +topk tail) -> attn
    m_kernel<<<dim3(LSEQ / MQT, BH), 1024, M_SMEM>>>(Q, K, idxs, u);
    attn_kernel<<<dim3(NCH, BH), 256, A_SMEM>>>(Q, K, V);

    // join: merge needs fill (output background) + attn partials
    cudaStreamWaitEvent(0, evJoin, 0);
    merge_kernel<<<dim3(USEL, BH), 64>>>(out);
}